// round 1
// baseline (speedup 1.0000x reference)
#include <cuda_runtime.h>
#include <cuda_bf16.h>
#include <math.h>

// ---------------------------------------------------------------------------
// Problem constants
// ---------------------------------------------------------------------------
#define N_TOK   4096
#define DIM     1024
#define INNER   1024
#define HEADS   16
#define HD      64
#define QKV_N   (3 * INNER)   // 3072

// Scratch buffers (no allocation allowed -> __device__ globals)
__device__ float g_qkv[N_TOK * QKV_N];    // 50.3 MB
__device__ float g_attn[N_TOK * INNER];   // 16.8 MB (also reused for h2)
__device__ float g_h1[N_TOK * INNER];     // 16.8 MB

// ---------------------------------------------------------------------------
// Generic 64x64 tiled fp32 GEMM:  C[M,N] = A[M,K] @ B[K,N]  (optional ReLU)
// 256 threads, 4x4 register tile per thread, BK=16, float4 smem traffic.
// M,N,K must be multiples of 64/64/16 (true for all uses here).
// ---------------------------------------------------------------------------
template <bool RELU>
__global__ void gemm64_kernel(const float* __restrict__ A,
                              const float* __restrict__ B,
                              float* __restrict__ C,
                              int M, int N, int K) {
    __shared__ float As[16][64];   // [k][m]
    __shared__ float Bs[16][64];   // [k][n]

    const int t  = threadIdx.x;
    const int tx = t & 15;
    const int ty = t >> 4;
    const int bm = blockIdx.y * 64;
    const int bn = blockIdx.x * 64;

    const int ar = t >> 2;          // 0..63  (A tile row)
    const int ac = (t & 3) << 2;    // 0,4,8,12 (A tile col base)
    const int br = t >> 4;          // 0..15  (B tile row)
    const int bc = (t & 15) << 2;   // 0..60  (B tile col base)

    float acc[4][4] = {};

    for (int k0 = 0; k0 < K; k0 += 16) {
        float4 a = *(const float4*)&A[(size_t)(bm + ar) * K + k0 + ac];
        As[ac + 0][ar] = a.x;
        As[ac + 1][ar] = a.y;
        As[ac + 2][ar] = a.z;
        As[ac + 3][ar] = a.w;
        *(float4*)&Bs[br][bc] = *(const float4*)&B[(size_t)(k0 + br) * N + bn + bc];
        __syncthreads();

#pragma unroll
        for (int kk = 0; kk < 16; kk++) {
            float4 av = *(float4*)&As[kk][ty << 2];
            float4 bv = *(float4*)&Bs[kk][tx << 2];
            float a0 = av.x, a1 = av.y, a2 = av.z, a3 = av.w;
            float b0 = bv.x, b1 = bv.y, b2 = bv.z, b3 = bv.w;
            acc[0][0] += a0 * b0; acc[0][1] += a0 * b1; acc[0][2] += a0 * b2; acc[0][3] += a0 * b3;
            acc[1][0] += a1 * b0; acc[1][1] += a1 * b1; acc[1][2] += a1 * b2; acc[1][3] += a1 * b3;
            acc[2][0] += a2 * b0; acc[2][1] += a2 * b1; acc[2][2] += a2 * b2; acc[2][3] += a2 * b3;
            acc[3][0] += a3 * b0; acc[3][1] += a3 * b1; acc[3][2] += a3 * b2; acc[3][3] += a3 * b3;
        }
        __syncthreads();
    }

#pragma unroll
    for (int i = 0; i < 4; i++) {
        float4 r;
        r.x = acc[i][0]; r.y = acc[i][1]; r.z = acc[i][2]; r.w = acc[i][3];
        if (RELU) {
            r.x = fmaxf(r.x, 0.f); r.y = fmaxf(r.y, 0.f);
            r.z = fmaxf(r.z, 0.f); r.w = fmaxf(r.w, 0.f);
        }
        *(float4*)&C[(size_t)(bm + (ty << 2) + i) * N + bn + (tx << 2)] = r;
    }
}

// ---------------------------------------------------------------------------
// RoPE applied in-place to q and k slices of qkv.
// thread -> (row, head, j) with j in [0,32)
// out[j]    = t[j]*cos - t[j+32]*sin
// out[j+32] = t[j+32]*cos + t[j]*sin
// ---------------------------------------------------------------------------
__global__ void rope_kernel(float* __restrict__ qkv) {
    int idx = blockIdx.x * blockDim.x + threadIdx.x;   // < 4096*16*32
    int row  = idx >> 9;
    int rem  = idx & 511;
    int head = rem >> 5;
    int j    = rem & 31;

    float inv_freq = powf(10000.f, -(float)(2 * j) * (1.f / 64.f));
    float fr = (float)row * inv_freq;
    float sv, cv;
    sincosf(fr, &sv, &cv);

    size_t base = (size_t)row * QKV_N + head * HD + j;
    float q1 = qkv[base], q2 = qkv[base + 32];
    qkv[base]      = q1 * cv - q2 * sv;
    qkv[base + 32] = q2 * cv + q1 * sv;

    float k1 = qkv[base + INNER], k2 = qkv[base + INNER + 32];
    qkv[base + INNER]      = k1 * cv - k2 * sv;
    qkv[base + INNER + 32] = k2 * cv + k1 * sv;
}

// ---------------------------------------------------------------------------
// Flash-attention (fp32, causal, tile 64x64, skips masked tiles).
// grid = (64 query tiles [reversed for balance], 16 heads), 256 threads.
// Thread (ty,tx) in 16x16 owns a 4x4 S tile and a 4x4 O tile.
// Dyn smem: qs/ks/vs 64x64 + ps 64x68 (padded) = 66560 B.
// ---------------------------------------------------------------------------
#define ATTN_SMEM ((3 * 64 * 64 + 64 * 68) * 4)

__global__ void attn_kernel(const float* __restrict__ qkv, float* __restrict__ out) {
    extern __shared__ float sm[];
    float* qs = sm;                 // 64x64 (scaled q)
    float* ks = sm + 4096;          // 64x64
    float* vs = sm + 8192;          // 64x64
    float* ps = sm + 12288;         // 64x68

    const int t  = threadIdx.x;
    const int tx = t & 15;
    const int ty = t >> 4;
    const int h  = blockIdx.y;
    const int qt = (int)gridDim.x - 1 - (int)blockIdx.x;  // long blocks first
    const int qbase = qt * 64;
    const int hoff  = h * HD;

    // load scaled Q tile
#pragma unroll
    for (int it = 0; it < 4; it++) {
        int idx = t + it * 256;
        int row = idx >> 4;
        int c4  = (idx & 15) << 2;
        float4 v = *(const float4*)&qkv[(size_t)(qbase + row) * QKV_N + hoff + c4];
        v.x *= 0.125f; v.y *= 0.125f; v.z *= 0.125f; v.w *= 0.125f;
        *(float4*)&qs[row * 64 + c4] = v;
    }

    float o[4][4] = {};
    float m[4], l[4];
#pragma unroll
    for (int i = 0; i < 4; i++) { m[i] = -1e30f; l[i] = 0.f; }

    for (int kt = 0; kt <= qt; kt++) {
        __syncthreads();   // previous iteration readers done
        // load K,V tiles
#pragma unroll
        for (int it = 0; it < 4; it++) {
            int idx = t + it * 256;
            int row = idx >> 4;
            int c4  = (idx & 15) << 2;
            size_t base = (size_t)(kt * 64 + row) * QKV_N + hoff + c4;
            *(float4*)&ks[row * 64 + c4] = *(const float4*)&qkv[base + INNER];
            *(float4*)&vs[row * 64 + c4] = *(const float4*)&qkv[base + 2 * INNER];
        }
        __syncthreads();

        // S = Q K^T (4x4 per thread)
        float s[4][4];
#pragma unroll
        for (int i = 0; i < 4; i++)
#pragma unroll
            for (int j = 0; j < 4; j++) s[i][j] = 0.f;

        for (int d4 = 0; d4 < 16; d4++) {
            float4 qv[4], kv[4];
#pragma unroll
            for (int i = 0; i < 4; i++) qv[i] = *(float4*)&qs[((ty << 2) + i) * 64 + (d4 << 2)];
#pragma unroll
            for (int j = 0; j < 4; j++) kv[j] = *(float4*)&ks[((tx << 2) + j) * 64 + (d4 << 2)];
#pragma unroll
            for (int i = 0; i < 4; i++)
#pragma unroll
                for (int j = 0; j < 4; j++)
                    s[i][j] += qv[i].x * kv[j].x + qv[i].y * kv[j].y +
                               qv[i].z * kv[j].z + qv[i].w * kv[j].w;
        }

        // causal mask only on the diagonal tile
        if (kt == qt) {
#pragma unroll
            for (int i = 0; i < 4; i++)
#pragma unroll
                for (int j = 0; j < 4; j++)
                    if (kt * 64 + (tx << 2) + j > qbase + (ty << 2) + i) s[i][j] = -1e30f;
        }

        // online softmax per row (4 rows per thread, 16 tx threads per row)
#pragma unroll
        for (int i = 0; i < 4; i++) {
            float rm = fmaxf(fmaxf(s[i][0], s[i][1]), fmaxf(s[i][2], s[i][3]));
            rm = fmaxf(rm, __shfl_xor_sync(0xffffffffu, rm, 1));
            rm = fmaxf(rm, __shfl_xor_sync(0xffffffffu, rm, 2));
            rm = fmaxf(rm, __shfl_xor_sync(0xffffffffu, rm, 4));
            rm = fmaxf(rm, __shfl_xor_sync(0xffffffffu, rm, 8));
            float mn = fmaxf(m[i], rm);
            float corr = expf(m[i] - mn);
            m[i] = mn;

            float4 p;
            p.x = expf(s[i][0] - mn);
            p.y = expf(s[i][1] - mn);
            p.z = expf(s[i][2] - mn);
            p.w = expf(s[i][3] - mn);
            float rs = p.x + p.y + p.z + p.w;
            rs += __shfl_xor_sync(0xffffffffu, rs, 1);
            rs += __shfl_xor_sync(0xffffffffu, rs, 2);
            rs += __shfl_xor_sync(0xffffffffu, rs, 4);
            rs += __shfl_xor_sync(0xffffffffu, rs, 8);
            l[i] = l[i] * corr + rs;

            *(float4*)&ps[((ty << 2) + i) * 68 + (tx << 2)] = p;
#pragma unroll
            for (int j = 0; j < 4; j++) o[i][j] *= corr;
        }
        __syncthreads();

        // O += P @ V  (4x4 per thread; thread cols now = head dims)
        for (int c4 = 0; c4 < 16; c4++) {
            float4 pv[4], vv[4];
#pragma unroll
            for (int i = 0; i < 4; i++) pv[i] = *(float4*)&ps[((ty << 2) + i) * 68 + (c4 << 2)];
#pragma unroll
            for (int cc = 0; cc < 4; cc++) vv[cc] = *(float4*)&vs[((c4 << 2) + cc) * 64 + (tx << 2)];
#pragma unroll
            for (int i = 0; i < 4; i++) {
                o[i][0] += pv[i].x * vv[0].x + pv[i].y * vv[1].x + pv[i].z * vv[2].x + pv[i].w * vv[3].x;
                o[i][1] += pv[i].x * vv[0].y + pv[i].y * vv[1].y + pv[i].z * vv[2].y + pv[i].w * vv[3].y;
                o[i][2] += pv[i].x * vv[0].z + pv[i].y * vv[1].z + pv[i].z * vv[2].z + pv[i].w * vv[3].z;
                o[i][3] += pv[i].x * vv[0].w + pv[i].y * vv[1].w + pv[i].z * vv[2].w + pv[i].w * vv[3].w;
            }
        }
    }

    // write O / l  -> [n, head*64+d]
#pragma unroll
    for (int i = 0; i < 4; i++) {
        float inv = 1.f / l[i];
        float4 r;
        r.x = o[i][0] * inv; r.y = o[i][1] * inv;
        r.z = o[i][2] * inv; r.w = o[i][3] * inv;
        *(float4*)&out[(size_t)(qbase + (ty << 2) + i) * INNER + hoff + (tx << 2)] = r;
    }
}

// ---------------------------------------------------------------------------
// LayerNorm over last dim (1024) with gamma, beta=0, eps=1e-5.
// One block per row, 256 threads, 4 values per thread.
// ---------------------------------------------------------------------------
__global__ void ln_kernel(const float* __restrict__ in,
                          const float* __restrict__ gamma,
                          float* __restrict__ out) {
    __shared__ float sbuf[8];
    const int row = blockIdx.x;
    const int t   = threadIdx.x;

    float4 v = *(const float4*)&in[(size_t)row * DIM + (t << 2)];

    float s = v.x + v.y + v.z + v.w;
#pragma unroll
    for (int o = 16; o; o >>= 1) s += __shfl_xor_sync(0xffffffffu, s, o);
    if ((t & 31) == 0) sbuf[t >> 5] = s;
    __syncthreads();
    float tot = sbuf[0] + sbuf[1] + sbuf[2] + sbuf[3] +
                sbuf[4] + sbuf[5] + sbuf[6] + sbuf[7];
    float mean = tot * (1.f / (float)DIM);
    __syncthreads();

    float dx = v.x - mean, dy = v.y - mean, dz = v.z - mean, dw = v.w - mean;
    float s2 = dx * dx + dy * dy + dz * dz + dw * dw;
#pragma unroll
    for (int o = 16; o; o >>= 1) s2 += __shfl_xor_sync(0xffffffffu, s2, o);
    if ((t & 31) == 0) sbuf[t >> 5] = s2;
    __syncthreads();
    float tot2 = sbuf[0] + sbuf[1] + sbuf[2] + sbuf[3] +
                 sbuf[4] + sbuf[5] + sbuf[6] + sbuf[7];
    float rstd = rsqrtf(tot2 * (1.f / (float)DIM) + 1e-5f);

    float4 g = *(const float4*)&gamma[t << 2];
    float4 r;
    r.x = dx * rstd * g.x;
    r.y = dy * rstd * g.y;
    r.z = dz * rstd * g.z;
    r.w = dw * rstd * g.w;
    *(float4*)&out[(size_t)row * DIM + (t << 2)] = r;
}

// ---------------------------------------------------------------------------
// launch
// ---------------------------------------------------------------------------
extern "C" void kernel_launch(void* const* d_in, const int* in_sizes, int n_in,
                              void* d_out, int out_size) {
    const float* x     = (const float*)d_in[0];
    const float* Wqkv  = (const float*)d_in[1];
    const float* Wo1   = (const float*)d_in[2];
    const float* Wo2   = (const float*)d_in[3];
    const float* gamma = (const float*)d_in[4];
    float* out = (float*)d_out;

    float *qkv, *attn, *h1;
    cudaGetSymbolAddress((void**)&qkv,  g_qkv);
    cudaGetSymbolAddress((void**)&attn, g_attn);
    cudaGetSymbolAddress((void**)&h1,   g_h1);

    cudaFuncSetAttribute(attn_kernel,
                         cudaFuncAttributeMaxDynamicSharedMemorySize, ATTN_SMEM);

    // 1) qkv = x @ W_qkv
    gemm64_kernel<false><<<dim3(QKV_N / 64, N_TOK / 64), 256>>>(x, Wqkv, qkv,
                                                                N_TOK, QKV_N, DIM);
    // 2) RoPE in-place on q,k
    rope_kernel<<<(N_TOK * HEADS * 32) / 256, 256>>>(qkv);
    // 3) causal flash attention -> attn [n, inner]
    attn_kernel<<<dim3(64, HEADS), 256, ATTN_SMEM>>>(qkv, attn);
    // 4) h1 = relu(attn @ W_o1)
    gemm64_kernel<true><<<dim3(DIM / 64, N_TOK / 64), 256>>>(attn, Wo1, h1,
                                                             N_TOK, DIM, INNER);
    // 5) h2 = h1 @ W_o2   (reuse attn buffer)
    gemm64_kernel<false><<<dim3(DIM / 64, N_TOK / 64), 256>>>(h1, Wo2, attn,
                                                              N_TOK, DIM, DIM);
    // 6) layernorm -> out
    ln_kernel<<<N_TOK, 256>>>(attn, gamma, out);
}

// round 3
// speedup vs baseline: 3.9867x; 3.9867x over previous
#include <cuda_runtime.h>
#include <cuda_bf16.h>
#include <math.h>
#include <stdint.h>

#define N_TOK   4096
#define DIM     1024
#define INNER   1024
#define HEADS   16
#define HD      64
#define QKV_N   (3 * INNER)

__device__ float g_qkv[N_TOK * QKV_N];
__device__ float g_attn[N_TOK * INNER];
__device__ float g_h1[N_TOK * INNER];

// ---------------------------------------------------------------------------
// helpers
// ---------------------------------------------------------------------------
__device__ __forceinline__ float bff(float x) {           // round-trip bf16
    return __bfloat162float(__float2bfloat16_rn(x));
}
__device__ __forceinline__ uint32_t pack2bf(float lo, float hi) {
    uint32_t r;
    asm("cvt.rn.bf16x2.f32 %0, %1, %2;" : "=r"(r) : "f"(hi), "f"(lo));
    return r;
}
__device__ __forceinline__ void mma_bf16(float* c, const uint32_t* a, const uint32_t* b) {
    asm volatile("mma.sync.aligned.m16n8k16.row.col.f32.bf16.bf16.f32 "
        "{%0,%1,%2,%3}, {%4,%5,%6,%7}, {%8,%9}, {%0,%1,%2,%3};"
        : "+f"(c[0]), "+f"(c[1]), "+f"(c[2]), "+f"(c[3])
        : "r"(a[0]), "r"(a[1]), "r"(a[2]), "r"(a[3]), "r"(b[0]), "r"(b[1]));
}

// ---------------------------------------------------------------------------
// Dense GEMM  C[M,N] = A[M,K] @ B[K,N], bf16-split mma, optional ReLU.
// Tile 128x128, BK=32, 8 warps (warp tile 64x32), double-buffered smem,
// register-prefetch pipeline. Requires M%128==0, N%128==0, K%32==0.
// Smem word layout per buffer: Ah[128*20] Al Bh Bl  (stride 20 words).
// ---------------------------------------------------------------------------
#define GS 20
#define GEMM_BUF_W (4 * 128 * GS)               // 10240 words
#define GEMM_SMEM  (2 * GEMM_BUF_W * 4)         // 81920 B

template <bool RELU>
__global__ void __launch_bounds__(256)
mma_gemm_kernel(const float* __restrict__ A, const float* __restrict__ B,
                float* __restrict__ C, int M, int N, int K) {
    extern __shared__ uint32_t sw[];
    const int t = threadIdx.x;
    const int lane = t & 31;
    const int wid = t >> 5;
    const int wm = wid & 1;        // 2 m-blocks of 64
    const int wn = wid >> 1;       // 4 n-blocks of 32
    const int bm = blockIdx.y * 128;
    const int bn = blockIdx.x * 128;
    const int nb = t & 31;         // B fill: n block (4 cols)
    const int kb = t >> 5;         // B fill: k block (4 rows)

    float4 pa[4], pb[4];

    auto ldg = [&](int c) {
#pragma unroll
        for (int i = 0; i < 4; i++) {
            int idx = i * 256 + t;
            int row = idx >> 3;
            int c4  = (idx & 7) << 2;
            pa[i] = *(const float4*)&A[(size_t)(bm + row) * K + c * 32 + c4];
        }
#pragma unroll
        for (int r = 0; r < 4; r++)
            pb[r] = *(const float4*)&B[(size_t)(c * 32 + kb * 4 + r) * N + bn + nb * 4];
    };

    auto sts = [&](uint32_t* buf) {
        uint32_t* Ah = buf;
        uint32_t* Al = buf + 2560;
        uint32_t* Bh = buf + 5120;
        uint32_t* Bl = buf + 7680;
#pragma unroll
        for (int i = 0; i < 4; i++) {
            int idx = i * 256 + t;
            int row = idx >> 3;
            int wc  = (idx & 7) << 1;
            float4 v = pa[i];
            uint2 h, l;
            h.x = pack2bf(v.x, v.y);
            h.y = pack2bf(v.z, v.w);
            l.x = pack2bf(v.x - bff(v.x), v.y - bff(v.y));
            l.y = pack2bf(v.z - bff(v.z), v.w - bff(v.w));
            *(uint2*)&Ah[row * GS + wc] = h;
            *(uint2*)&Al[row * GS + wc] = l;
        }
#pragma unroll
        for (int j = 0; j < 4; j++) {
            float b0 = ((const float*)&pb[0])[j];
            float b1 = ((const float*)&pb[1])[j];
            float b2 = ((const float*)&pb[2])[j];
            float b3 = ((const float*)&pb[3])[j];
            uint2 h, l;
            h.x = pack2bf(b0, b1);
            h.y = pack2bf(b2, b3);
            l.x = pack2bf(b0 - bff(b0), b1 - bff(b1));
            l.y = pack2bf(b2 - bff(b2), b3 - bff(b3));
            *(uint2*)&Bh[(nb * 4 + j) * GS + kb * 2] = h;
            *(uint2*)&Bl[(nb * 4 + j) * GS + kb * 2] = l;
        }
    };

    float acc[4][4][4];
#pragma unroll
    for (int i = 0; i < 4; i++)
#pragma unroll
        for (int j = 0; j < 4; j++)
#pragma unroll
            for (int r = 0; r < 4; r++) acc[i][j][r] = 0.f;

    const int nch = K / 32;

    ldg(0);
    sts(sw);
    __syncthreads();

    for (int c = 0; c < nch; c++) {
        if (c + 1 < nch) ldg(c + 1);

        uint32_t* buf = sw + (c & 1) * GEMM_BUF_W;
        uint32_t* Ah = buf;
        uint32_t* Al = buf + 2560;
        uint32_t* Bh = buf + 5120;
        uint32_t* Bl = buf + 7680;

#pragma unroll
        for (int ks = 0; ks < 2; ks++) {
            uint32_t ah[4][4], al[4][4], bh[4][2], bl[4][2];
#pragma unroll
            for (int mt = 0; mt < 4; mt++) {
                int base = (wm * 64 + mt * 16 + (lane >> 2)) * GS + ks * 8 + (lane & 3);
                ah[mt][0] = Ah[base];
                ah[mt][1] = Ah[base + 8 * GS];
                ah[mt][2] = Ah[base + 4];
                ah[mt][3] = Ah[base + 8 * GS + 4];
                al[mt][0] = Al[base];
                al[mt][1] = Al[base + 8 * GS];
                al[mt][2] = Al[base + 4];
                al[mt][3] = Al[base + 8 * GS + 4];
            }
#pragma unroll
            for (int nt = 0; nt < 4; nt++) {
                int base = (wn * 32 + nt * 8 + (lane >> 2)) * GS + ks * 8 + (lane & 3);
                bh[nt][0] = Bh[base];
                bh[nt][1] = Bh[base + 4];
                bl[nt][0] = Bl[base];
                bl[nt][1] = Bl[base + 4];
            }
#pragma unroll
            for (int mt = 0; mt < 4; mt++)
#pragma unroll
                for (int nt = 0; nt < 4; nt++) {
                    mma_bf16(acc[mt][nt], ah[mt], bh[nt]);
                    mma_bf16(acc[mt][nt], al[mt], bh[nt]);
                    mma_bf16(acc[mt][nt], ah[mt], bl[nt]);
                }
        }

        if (c + 1 < nch) {
            sts(sw + ((c + 1) & 1) * GEMM_BUF_W);
            __syncthreads();
        }
    }

#pragma unroll
    for (int mt = 0; mt < 4; mt++)
#pragma unroll
        for (int nt = 0; nt < 4; nt++) {
            int row = bm + wm * 64 + mt * 16 + (lane >> 2);
            int col = bn + wn * 32 + nt * 8 + 2 * (lane & 3);
            float2 v01, v23;
            v01.x = acc[mt][nt][0]; v01.y = acc[mt][nt][1];
            v23.x = acc[mt][nt][2]; v23.y = acc[mt][nt][3];
            if (RELU) {
                v01.x = fmaxf(v01.x, 0.f); v01.y = fmaxf(v01.y, 0.f);
                v23.x = fmaxf(v23.x, 0.f); v23.y = fmaxf(v23.y, 0.f);
            }
            *(float2*)&C[(size_t)row * N + col] = v01;
            *(float2*)&C[(size_t)(row + 8) * N + col] = v23;
        }
}

// ---------------------------------------------------------------------------
// RoPE (unchanged)
// ---------------------------------------------------------------------------
__global__ void rope_kernel(float* __restrict__ qkv) {
    int idx = blockIdx.x * blockDim.x + threadIdx.x;
    int row  = idx >> 9;
    int rem  = idx & 511;
    int head = rem >> 5;
    int j    = rem & 31;

    float inv_freq = powf(10000.f, -(float)(2 * j) * (1.f / 64.f));
    float fr = (float)row * inv_freq;
    float sv, cv;
    sincosf(fr, &sv, &cv);

    size_t base = (size_t)row * QKV_N + head * HD + j;
    float q1 = qkv[base], q2 = qkv[base + 32];
    qkv[base]      = q1 * cv - q2 * sv;
    qkv[base + 32] = q2 * cv + q1 * sv;

    float k1 = qkv[base + INNER], k2 = qkv[base + INNER + 32];
    qkv[base + INNER]      = k1 * cv - k2 * sv;
    qkv[base + INNER + 32] = k2 * cv + k1 * sv;
}

// ---------------------------------------------------------------------------
// Flash attention with bf16-split mma.
// Block: 4 warps, 64 q-rows, one head. Warp owns 16 q-rows.
// Smem (uint32 words, stride 36): Qh Ql Kh Kl (rows=seq, words=d/2)
//                                 Vh Vl (rows=d, words=kv/2, transposed-packed)
// ---------------------------------------------------------------------------
#define AS 36
#define ATT_TILE_W (64 * AS)
#define ATTN_SMEM (6 * ATT_TILE_W * 4)     // 55296 B

__global__ void __launch_bounds__(128)
attn_kernel(const float* __restrict__ qkv, float* __restrict__ out) {
    extern __shared__ uint32_t sw[];
    uint32_t* Qh = sw;
    uint32_t* Ql = sw + ATT_TILE_W;
    uint32_t* Kh = sw + 2 * ATT_TILE_W;
    uint32_t* Kl = sw + 3 * ATT_TILE_W;
    uint32_t* Vh = sw + 4 * ATT_TILE_W;
    uint32_t* Vl = sw + 5 * ATT_TILE_W;

    const int t = threadIdx.x;
    const int lane = t & 31;
    const int wid = t >> 5;
    const int h = blockIdx.y;
    const int qt = (int)gridDim.x - 1 - (int)blockIdx.x;
    const int qbase = qt * 64;
    const int hoff = h * HD;

    // ---- Q fill (scaled by 1/8), split hi/lo ----
#pragma unroll
    for (int i = 0; i < 8; i++) {
        int idx = i * 128 + t;
        int row = idx >> 4;
        int c4  = (idx & 15) << 2;
        float4 v = *(const float4*)&qkv[(size_t)(qbase + row) * QKV_N + hoff + c4];
        v.x *= 0.125f; v.y *= 0.125f; v.z *= 0.125f; v.w *= 0.125f;
        uint2 hw, lw;
        hw.x = pack2bf(v.x, v.y);
        hw.y = pack2bf(v.z, v.w);
        lw.x = pack2bf(v.x - bff(v.x), v.y - bff(v.y));
        lw.y = pack2bf(v.z - bff(v.z), v.w - bff(v.w));
        *(uint2*)&Qh[row * AS + (c4 >> 1)] = hw;
        *(uint2*)&Ql[row * AS + (c4 >> 1)] = lw;
    }
    __syncthreads();

    // ---- hoist Q fragments ----
    uint32_t qh[4][4], ql[4][4];
#pragma unroll
    for (int kc = 0; kc < 4; kc++) {
        int base = (wid * 16 + (lane >> 2)) * AS + kc * 8 + (lane & 3);
        qh[kc][0] = Qh[base];
        qh[kc][1] = Qh[base + 8 * AS];
        qh[kc][2] = Qh[base + 4];
        qh[kc][3] = Qh[base + 8 * AS + 4];
        ql[kc][0] = Ql[base];
        ql[kc][1] = Ql[base + 8 * AS];
        ql[kc][2] = Ql[base + 4];
        ql[kc][3] = Ql[base + 8 * AS + 4];
    }

    float o[8][4];
#pragma unroll
    for (int nt = 0; nt < 8; nt++)
#pragma unroll
        for (int r = 0; r < 4; r++) o[nt][r] = 0.f;
    float m0 = -1e30f, m1 = -1e30f, l0 = 0.f, l1 = 0.f;

    for (int kt = 0; kt <= qt; kt++) {
        __syncthreads();
        // ---- K fill ----
#pragma unroll
        for (int i = 0; i < 8; i++) {
            int idx = i * 128 + t;
            int row = idx >> 4;
            int c4  = (idx & 15) << 2;
            float4 v = *(const float4*)&qkv[(size_t)(kt * 64 + row) * QKV_N + hoff + INNER + c4];
            uint2 hw, lw;
            hw.x = pack2bf(v.x, v.y);
            hw.y = pack2bf(v.z, v.w);
            lw.x = pack2bf(v.x - bff(v.x), v.y - bff(v.y));
            lw.y = pack2bf(v.z - bff(v.z), v.w - bff(v.w));
            *(uint2*)&Kh[row * AS + (c4 >> 1)] = hw;
            *(uint2*)&Kl[row * AS + (c4 >> 1)] = lw;
        }
        // ---- V fill (transposed-packed: Vs[d][kv-pair]) ----
#pragma unroll
        for (int i = 0; i < 4; i++) {
            int idx = i * 128 + t;
            int kvp = idx & 31;
            int d0  = (idx >> 5) << 2;
            const float* vp = &qkv[(size_t)(kt * 64 + 2 * kvp) * QKV_N + hoff + 2 * INNER + d0];
            float4 r0 = *(const float4*)vp;
            float4 r1 = *(const float4*)(vp + QKV_N);
#pragma unroll
            for (int j = 0; j < 4; j++) {
                float a = ((const float*)&r0)[j];
                float b = ((const float*)&r1)[j];
                Vh[(d0 + j) * AS + kvp] = pack2bf(a, b);
                Vl[(d0 + j) * AS + kvp] = pack2bf(a - bff(a), b - bff(b));
            }
        }
        __syncthreads();

        // ---- S = Q K^T ----
        float s[8][4];
#pragma unroll
        for (int nt = 0; nt < 8; nt++)
#pragma unroll
            for (int r = 0; r < 4; r++) s[nt][r] = 0.f;

#pragma unroll
        for (int kc = 0; kc < 4; kc++) {
#pragma unroll
            for (int nt = 0; nt < 8; nt++) {
                int kb = (nt * 8 + (lane >> 2)) * AS + kc * 8 + (lane & 3);
                uint32_t bh[2], bl[2];
                bh[0] = Kh[kb]; bh[1] = Kh[kb + 4];
                bl[0] = Kl[kb]; bl[1] = Kl[kb + 4];
                mma_bf16(s[nt], qh[kc], bh);
                mma_bf16(s[nt], ql[kc], bh);
                mma_bf16(s[nt], qh[kc], bl);
            }
        }

        // ---- causal mask (diagonal tile only) ----
        if (kt == qt) {
            int r0 = wid * 16 + (lane >> 2);
            int r1 = r0 + 8;
#pragma unroll
            for (int nt = 0; nt < 8; nt++) {
                int c0 = nt * 8 + 2 * (lane & 3);
                if (c0 > r0)     s[nt][0] = -1e30f;
                if (c0 + 1 > r0) s[nt][1] = -1e30f;
                if (c0 > r1)     s[nt][2] = -1e30f;
                if (c0 + 1 > r1) s[nt][3] = -1e30f;
            }
        }

        // ---- online softmax (intra-warp, quad reduces) ----
        float rm0 = -1e30f, rm1 = -1e30f;
#pragma unroll
        for (int nt = 0; nt < 8; nt++) {
            rm0 = fmaxf(rm0, fmaxf(s[nt][0], s[nt][1]));
            rm1 = fmaxf(rm1, fmaxf(s[nt][2], s[nt][3]));
        }
        rm0 = fmaxf(rm0, __shfl_xor_sync(0xffffffffu, rm0, 1));
        rm0 = fmaxf(rm0, __shfl_xor_sync(0xffffffffu, rm0, 2));
        rm1 = fmaxf(rm1, __shfl_xor_sync(0xffffffffu, rm1, 1));
        rm1 = fmaxf(rm1, __shfl_xor_sync(0xffffffffu, rm1, 2));
        float mn0 = fmaxf(m0, rm0), mn1 = fmaxf(m1, rm1);
        float corr0 = __expf(m0 - mn0), corr1 = __expf(m1 - mn1);
        m0 = mn0; m1 = mn1;

        float sum0 = 0.f, sum1 = 0.f;
#pragma unroll
        for (int nt = 0; nt < 8; nt++) {
            s[nt][0] = __expf(s[nt][0] - mn0);
            s[nt][1] = __expf(s[nt][1] - mn0);
            s[nt][2] = __expf(s[nt][2] - mn1);
            s[nt][3] = __expf(s[nt][3] - mn1);
            sum0 += s[nt][0] + s[nt][1];
            sum1 += s[nt][2] + s[nt][3];
        }
        sum0 += __shfl_xor_sync(0xffffffffu, sum0, 1);
        sum0 += __shfl_xor_sync(0xffffffffu, sum0, 2);
        sum1 += __shfl_xor_sync(0xffffffffu, sum1, 1);
        sum1 += __shfl_xor_sync(0xffffffffu, sum1, 2);
        l0 = l0 * corr0 + sum0;
        l1 = l1 * corr1 + sum1;
#pragma unroll
        for (int nt = 0; nt < 8; nt++) {
            o[nt][0] *= corr0; o[nt][1] *= corr0;
            o[nt][2] *= corr1; o[nt][3] *= corr1;
        }

        // ---- O += P V  (P from registers: C-frag == A-frag layout) ----
#pragma unroll
        for (int kc = 0; kc < 4; kc++) {
            const float* sa = s[2 * kc];
            const float* sb = s[2 * kc + 1];
            uint32_t ph[4], pl[4];
            ph[0] = pack2bf(sa[0], sa[1]);
            ph[1] = pack2bf(sa[2], sa[3]);
            ph[2] = pack2bf(sb[0], sb[1]);
            ph[3] = pack2bf(sb[2], sb[3]);
            pl[0] = pack2bf(sa[0] - bff(sa[0]), sa[1] - bff(sa[1]));
            pl[1] = pack2bf(sa[2] - bff(sa[2]), sa[3] - bff(sa[3]));
            pl[2] = pack2bf(sb[0] - bff(sb[0]), sb[1] - bff(sb[1]));
            pl[3] = pack2bf(sb[2] - bff(sb[2]), sb[3] - bff(sb[3]));
#pragma unroll
            for (int nt = 0; nt < 8; nt++) {
                int vb = (nt * 8 + (lane >> 2)) * AS + kc * 8 + (lane & 3);
                uint32_t vh[2], vl[2];
                vh[0] = Vh[vb]; vh[1] = Vh[vb + 4];
                vl[0] = Vl[vb]; vl[1] = Vl[vb + 4];
                mma_bf16(o[nt], ph, vh);
                mma_bf16(o[nt], ph, vl);
                mma_bf16(o[nt], pl, vh);
            }
        }
    }

    // ---- write out ----
    float inv0 = 1.f / l0, inv1 = 1.f / l1;
    int row = qbase + wid * 16 + (lane >> 2);
#pragma unroll
    for (int nt = 0; nt < 8; nt++) {
        int col = hoff + nt * 8 + 2 * (lane & 3);
        float2 v01, v23;
        v01.x = o[nt][0] * inv0; v01.y = o[nt][1] * inv0;
        v23.x = o[nt][2] * inv1; v23.y = o[nt][3] * inv1;
        *(float2*)&out[(size_t)row * INNER + col] = v01;
        *(float2*)&out[(size_t)(row + 8) * INNER + col] = v23;
    }
}

// ---------------------------------------------------------------------------
// LayerNorm (unchanged)
// ---------------------------------------------------------------------------
__global__ void ln_kernel(const float* __restrict__ in,
                          const float* __restrict__ gamma,
                          float* __restrict__ out) {
    __shared__ float sbuf[8];
    const int row = blockIdx.x;
    const int t   = threadIdx.x;

    float4 v = *(const float4*)&in[(size_t)row * DIM + (t << 2)];

    float s = v.x + v.y + v.z + v.w;
#pragma unroll
    for (int o = 16; o; o >>= 1) s += __shfl_xor_sync(0xffffffffu, s, o);
    if ((t & 31) == 0) sbuf[t >> 5] = s;
    __syncthreads();
    float tot = sbuf[0] + sbuf[1] + sbuf[2] + sbuf[3] +
                sbuf[4] + sbuf[5] + sbuf[6] + sbuf[7];
    float mean = tot * (1.f / (float)DIM);
    __syncthreads();

    float dx = v.x - mean, dy = v.y - mean, dz = v.z - mean, dw = v.w - mean;
    float s2 = dx * dx + dy * dy + dz * dz + dw * dw;
#pragma unroll
    for (int o = 16; o; o >>= 1) s2 += __shfl_xor_sync(0xffffffffu, s2, o);
    if ((t & 31) == 0) sbuf[t >> 5] = s2;
    __syncthreads();
    float tot2 = sbuf[0] + sbuf[1] + sbuf[2] + sbuf[3] +
                 sbuf[4] + sbuf[5] + sbuf[6] + sbuf[7];
    float rstd = rsqrtf(tot2 * (1.f / (float)DIM) + 1e-5f);

    float4 g = *(const float4*)&gamma[t << 2];
    float4 r;
    r.x = dx * rstd * g.x;
    r.y = dy * rstd * g.y;
    r.z = dz * rstd * g.z;
    r.w = dw * rstd * g.w;
    *(float4*)&out[(size_t)row * DIM + (t << 2)] = r;
}

// ---------------------------------------------------------------------------
// launch
// ---------------------------------------------------------------------------
extern "C" void kernel_launch(void* const* d_in, const int* in_sizes, int n_in,
                              void* d_out, int out_size) {
    const float* x     = (const float*)d_in[0];
    const float* Wqkv  = (const float*)d_in[1];
    const float* Wo1   = (const float*)d_in[2];
    const float* Wo2   = (const float*)d_in[3];
    const float* gamma = (const float*)d_in[4];
    float* out = (float*)d_out;

    float *qkv, *attn, *h1;
    cudaGetSymbolAddress((void**)&qkv,  g_qkv);
    cudaGetSymbolAddress((void**)&attn, g_attn);
    cudaGetSymbolAddress((void**)&h1,   g_h1);

    static bool attr_done = false;
    if (!attr_done) {
        cudaFuncSetAttribute(attn_kernel,
                             cudaFuncAttributeMaxDynamicSharedMemorySize, ATTN_SMEM);
        cudaFuncSetAttribute(mma_gemm_kernel<false>,
                             cudaFuncAttributeMaxDynamicSharedMemorySize, GEMM_SMEM);
        cudaFuncSetAttribute(mma_gemm_kernel<true>,
                             cudaFuncAttributeMaxDynamicSharedMemorySize, GEMM_SMEM);
        attr_done = true;
    }

    mma_gemm_kernel<false><<<dim3(QKV_N / 128, N_TOK / 128), 256, GEMM_SMEM>>>(
        x, Wqkv, qkv, N_TOK, QKV_N, DIM);
    rope_kernel<<<(N_TOK * HEADS * 32) / 256, 256>>>(qkv);
    attn_kernel<<<dim3(64, HEADS), 128, ATTN_SMEM>>>(qkv, attn);
    mma_gemm_kernel<true><<<dim3(DIM / 128, N_TOK / 128), 256, GEMM_SMEM>>>(
        attn, Wo1, h1, N_TOK, DIM, INNER);
    mma_gemm_kernel<false><<<dim3(DIM / 128, N_TOK / 128), 256, GEMM_SMEM>>>(
        h1, Wo2, attn, N_TOK, DIM, DIM);
    ln_kernel<<<N_TOK, 256>>>(attn, gamma, out);
}

// round 4
// speedup vs baseline: 4.6554x; 1.1677x over previous
#include <cuda_runtime.h>
#include <cuda_bf16.h>
#include <math.h>
#include <stdint.h>

#define N_TOK   4096
#define DIM     1024
#define HEADS   16
#define HD      64
#define QKV_N   3072
#define KW      (DIM / 2)          // 512 words per 1024-dim row

// ---------------------------------------------------------------------------
// Scratch (no allocation allowed)
// ---------------------------------------------------------------------------
__device__ float    g_qkv[N_TOK * QKV_N];      // fp32 staging after QKV gemm
__device__ float    g_h2[N_TOK * DIM];         // pre-LN output
__device__ uint32_t g_XH[N_TOK * KW],  g_XL[N_TOK * KW];
__device__ uint32_t g_QH[N_TOK * KW],  g_QL[N_TOK * KW];
__device__ uint32_t g_KH[N_TOK * KW],  g_KL[N_TOK * KW];
__device__ uint32_t g_VH[HEADS * 64 * 2048], g_VL[HEADS * 64 * 2048];
__device__ uint32_t g_AtH[N_TOK * KW], g_AtL[N_TOK * KW];
__device__ uint32_t g_H1H[N_TOK * KW], g_H1L[N_TOK * KW];
__device__ uint32_t g_WqkvH[QKV_N * KW], g_WqkvL[QKV_N * KW];
__device__ uint32_t g_Wo1H[DIM * KW], g_Wo1L[DIM * KW];
__device__ uint32_t g_Wo2H[DIM * KW], g_Wo2L[DIM * KW];

// ---------------------------------------------------------------------------
// helpers
// ---------------------------------------------------------------------------
__device__ __forceinline__ float bff(float x) {
    return __bfloat162float(__float2bfloat16_rn(x));
}
__device__ __forceinline__ uint32_t pack2bf(float lo, float hi) {  // lo->bits[0:16)
    uint32_t r;
    asm("cvt.rn.bf16x2.f32 %0, %1, %2;" : "=r"(r) : "f"(hi), "f"(lo));
    return r;
}
__device__ __forceinline__ uint32_t packlo(float a, float b) {     // residuals
    return pack2bf(a - bff(a), b - bff(b));
}
__device__ __forceinline__ void mma_bf16(float* c, const uint32_t* a, const uint32_t* b) {
    asm volatile("mma.sync.aligned.m16n8k16.row.col.f32.bf16.bf16.f32 "
        "{%0,%1,%2,%3}, {%4,%5,%6,%7}, {%8,%9}, {%0,%1,%2,%3};"
        : "+f"(c[0]), "+f"(c[1]), "+f"(c[2]), "+f"(c[3])
        : "r"(a[0]), "r"(a[1]), "r"(a[2]), "r"(a[3]), "r"(b[0]), "r"(b[1]));
}
__device__ __forceinline__ uint32_t smem_u32(const void* p) {
    uint32_t a;
    asm("{ .reg .u64 t; cvta.to.shared.u64 t, %1; cvt.u32.u64 %0, t; }"
        : "=r"(a) : "l"(p));
    return a;
}
#define CP_ASYNC16(dst, src) \
    asm volatile("cp.async.cg.shared.global [%0], [%1], 16;" :: "r"(dst), "l"(src))
#define CP_COMMIT() asm volatile("cp.async.commit_group;")
#define CP_WAIT0()  asm volatile("cp.async.wait_group 0;")
#define CP_WAIT1()  asm volatile("cp.async.wait_group 1;")

// ---------------------------------------------------------------------------
// Prep: split x -> XH/XL  ([4096][512] packed bf16x2 words)
// ---------------------------------------------------------------------------
__global__ void split_x_kernel(const float* __restrict__ x) {
    int idx = blockIdx.x * 256 + threadIdx.x;       // < N_TOK*KW
    float2 v = *(const float2*)&x[(size_t)idx * 2];
    g_XH[idx] = pack2bf(v.x, v.y);
    g_XL[idx] = packlo(v.x, v.y);
}

// ---------------------------------------------------------------------------
// Prep: split + transpose weights  W[K][N] -> H/L [N][K/2]
// Block handles 64k x 64n tile; grid (N/64, K/64).
// ---------------------------------------------------------------------------
__global__ void split_w_kernel(const float* __restrict__ W,
                               uint32_t* __restrict__ H, uint32_t* __restrict__ L,
                               int K, int N) {
    __shared__ float S[64][68];
    const int t = threadIdx.x;
    const int k0 = blockIdx.y * 64, n0 = blockIdx.x * 64;
#pragma unroll
    for (int i = 0; i < 4; i++) {
        int slot = i * 256 + t;
        int k = slot >> 4, n4 = (slot & 15) << 2;
        *(float4*)&S[k][n4] = *(const float4*)&W[(size_t)(k0 + k) * N + n0 + n4];
    }
    __syncthreads();
    const int kw = K >> 1;
#pragma unroll
    for (int i = 0; i < 8; i++) {
        int slot = i * 256 + t;
        int n = slot >> 5, kwl = slot & 31;
        float a = S[2 * kwl][n], b = S[2 * kwl + 1][n];
        size_t o = (size_t)(n0 + n) * kw + (k0 >> 1) + kwl;
        H[o] = pack2bf(a, b);
        L[o] = packlo(a, b);
    }
}

// ---------------------------------------------------------------------------
// Prep: RoPE + split Q,K  (Q scaled by 1/8)
// ---------------------------------------------------------------------------
__global__ void rope_split_kernel() {
    int idx = blockIdx.x * 256 + threadIdx.x;       // < N_TOK*KW (2M)
    int row  = idx >> 9;
    int hw   = idx & 511;
    int head = hw >> 5;
    int w    = hw & 31;
    int d0   = w * 2;
    int i0   = d0 & 31;

    float invf0 = powf(10000.f, -(float)i0 * (1.f / 32.f));
    float invf1 = powf(10000.f, -(float)(i0 + 1) * (1.f / 32.f));
    float s0, c0, s1, c1;
    sincosf((float)row * invf0, &s0, &c0);
    sincosf((float)row * invf1, &s1, &c1);

    bool half = (d0 < 32);
    size_t base = (size_t)row * QKV_N + head * HD + d0;
    size_t pb   = half ? base + 32 : base - 32;

    float q0 = g_qkv[base],     q1 = g_qkv[base + 1];
    float qp0 = g_qkv[pb],      qp1 = g_qkv[pb + 1];
    float k0 = g_qkv[base + DIM],     k1 = g_qkv[base + DIM + 1];
    float kp0 = g_qkv[pb + DIM],      kp1 = g_qkv[pb + DIM + 1];

    float oq0, oq1, ok0, ok1;
    if (half) {
        oq0 = q0 * c0 - qp0 * s0;  oq1 = q1 * c1 - qp1 * s1;
        ok0 = k0 * c0 - kp0 * s0;  ok1 = k1 * c1 - kp1 * s1;
    } else {
        oq0 = q0 * c0 + qp0 * s0;  oq1 = q1 * c1 + qp1 * s1;
        ok0 = k0 * c0 + kp0 * s0;  ok1 = k1 * c1 + kp1 * s1;
    }
    oq0 *= 0.125f; oq1 *= 0.125f;

    g_QH[idx] = pack2bf(oq0, oq1);
    g_QL[idx] = packlo(oq0, oq1);
    g_KH[idx] = pack2bf(ok0, ok1);
    g_KL[idx] = packlo(ok0, ok1);
}

// ---------------------------------------------------------------------------
// Prep: V -> transposed-packed split tiles.
// grid (64 tiles, 16 heads). Tile (head h, kt): Vt[d=64][pair=32] words.
// ---------------------------------------------------------------------------
__global__ void v_prep_kernel() {
    __shared__ float S[64][68];
    const int t = threadIdx.x;
    const int kt = blockIdx.x, h = blockIdx.y;
#pragma unroll
    for (int i = 0; i < 4; i++) {
        int slot = i * 256 + t;
        int r = slot >> 4, c4 = (slot & 15) << 2;
        *(float4*)&S[r][c4] =
            *(const float4*)&g_qkv[(size_t)(kt * 64 + r) * QKV_N + 2 * DIM + h * HD + c4];
    }
    __syncthreads();
    size_t tb = ((size_t)(h * 64 + kt)) << 11;      // *2048
#pragma unroll
    for (int i = 0; i < 8; i++) {
        int slot = i * 256 + t;
        int d = slot >> 5, p = slot & 31;
        float a = S[2 * p][d], b = S[2 * p + 1][d];
        g_VH[tb + slot] = pack2bf(a, b);
        g_VL[tb + slot] = packlo(a, b);
    }
}

// ---------------------------------------------------------------------------
// GEMM on pre-split operands: C = A @ B^T-layout, 3-term bf16 split.
// A planes [M][K/2], B planes [N][K/2]. Tile 128x128, BK=32, 512 thr/16 warps.
// MODE 0: write fp32 C.  MODE 1: relu + write split planes CH/CL.
// ---------------------------------------------------------------------------
#define GS 20
#define GEMM_BUF_W (4 * 128 * GS)               // 10240 words per buffer
#define GEMM_SMEM  (2 * GEMM_BUF_W * 4)         // 81920 B

template <int MODE>
__global__ void __launch_bounds__(512)
gemm_pre(const uint32_t* __restrict__ AH, const uint32_t* __restrict__ AL,
         const uint32_t* __restrict__ BH, const uint32_t* __restrict__ BL,
         float* __restrict__ Cf, uint32_t* __restrict__ CH, uint32_t* __restrict__ CL,
         int M, int N, int K) {
    extern __shared__ uint32_t sw[];
    const int kw = K >> 1;
    const int t = threadIdx.x;
    const int lane = t & 31;
    const int wid = t >> 5;
    const int wm = wid & 3;         // 4 m-blocks of 32
    const int wn = wid >> 2;        // 4 n-blocks of 32
    const int bm = blockIdx.y * 128;
    const int bn = blockIdx.x * 128;
    const uint32_t sb = smem_u32(sw);

    const int frow = t >> 2;
    const int fw4  = (t & 3) << 2;
    const uint32_t* sAH = &AH[(size_t)(bm + frow) * kw + fw4];
    const uint32_t* sAL = &AL[(size_t)(bm + frow) * kw + fw4];
    const uint32_t* sBH = &BH[(size_t)(bn + frow) * kw + fw4];
    const uint32_t* sBL = &BL[(size_t)(bn + frow) * kw + fw4];
    const uint32_t dbase = sb + (frow * GS + fw4) * 4;

    auto issue = [&](int c) {
        uint32_t d = dbase + ((c & 1) * GEMM_BUF_W) * 4;
        int go = c * 16;
        CP_ASYNC16(d,            sAH + go);
        CP_ASYNC16(d + 2560 * 4, sAL + go);
        CP_ASYNC16(d + 5120 * 4, sBH + go);
        CP_ASYNC16(d + 7680 * 4, sBL + go);
    };

    float acc[2][4][4];
#pragma unroll
    for (int i = 0; i < 2; i++)
#pragma unroll
        for (int j = 0; j < 4; j++)
#pragma unroll
            for (int r = 0; r < 4; r++) acc[i][j][r] = 0.f;

    const int nch = K / 32;
    issue(0); CP_COMMIT();

    for (int c = 0; c < nch; c++) {
        if (c + 1 < nch) { issue(c + 1); CP_COMMIT(); CP_WAIT1(); }
        else             { CP_WAIT0(); }
        __syncthreads();

        uint32_t* buf = sw + (c & 1) * GEMM_BUF_W;
        uint32_t* Ah = buf;
        uint32_t* Al = buf + 2560;
        uint32_t* Bh = buf + 5120;
        uint32_t* Bl = buf + 7680;

#pragma unroll
        for (int ks = 0; ks < 2; ks++) {
            uint32_t ah[2][4], al[2][4], bh[4][2], bl[4][2];
#pragma unroll
            for (int mt = 0; mt < 2; mt++) {
                int base = (wm * 32 + mt * 16 + (lane >> 2)) * GS + ks * 8 + (lane & 3);
                ah[mt][0] = Ah[base];
                ah[mt][1] = Ah[base + 8 * GS];
                ah[mt][2] = Ah[base + 4];
                ah[mt][3] = Ah[base + 8 * GS + 4];
                al[mt][0] = Al[base];
                al[mt][1] = Al[base + 8 * GS];
                al[mt][2] = Al[base + 4];
                al[mt][3] = Al[base + 8 * GS + 4];
            }
#pragma unroll
            for (int nt = 0; nt < 4; nt++) {
                int base = (wn * 32 + nt * 8 + (lane >> 2)) * GS + ks * 8 + (lane & 3);
                bh[nt][0] = Bh[base];
                bh[nt][1] = Bh[base + 4];
                bl[nt][0] = Bl[base];
                bl[nt][1] = Bl[base + 4];
            }
#pragma unroll
            for (int mt = 0; mt < 2; mt++)
#pragma unroll
                for (int nt = 0; nt < 4; nt++) {
                    mma_bf16(acc[mt][nt], ah[mt], bh[nt]);
                    mma_bf16(acc[mt][nt], al[mt], bh[nt]);
                    mma_bf16(acc[mt][nt], ah[mt], bl[nt]);
                }
        }
        __syncthreads();
    }

#pragma unroll
    for (int mt = 0; mt < 2; mt++)
#pragma unroll
        for (int nt = 0; nt < 4; nt++) {
            int row = bm + wm * 32 + mt * 16 + (lane >> 2);
            int col = bn + wn * 32 + nt * 8 + 2 * (lane & 3);
            float v0 = acc[mt][nt][0], v1 = acc[mt][nt][1];
            float v2 = acc[mt][nt][2], v3 = acc[mt][nt][3];
            if (MODE == 1) {
                v0 = fmaxf(v0, 0.f); v1 = fmaxf(v1, 0.f);
                v2 = fmaxf(v2, 0.f); v3 = fmaxf(v3, 0.f);
                int wc = col >> 1;
                CH[(size_t)row * (N >> 1) + wc]       = pack2bf(v0, v1);
                CL[(size_t)row * (N >> 1) + wc]       = packlo(v0, v1);
                CH[(size_t)(row + 8) * (N >> 1) + wc] = pack2bf(v2, v3);
                CL[(size_t)(row + 8) * (N >> 1) + wc] = packlo(v2, v3);
            } else {
                *(float2*)&Cf[(size_t)row * N + col]       = make_float2(v0, v1);
                *(float2*)&Cf[(size_t)(row + 8) * N + col] = make_float2(v2, v3);
            }
        }
}

// ---------------------------------------------------------------------------
// Flash attention on pre-split operands. 4 warps, 64 q rows, one head.
// Writes split output planes AtH/AtL directly.
// ---------------------------------------------------------------------------
#define AS 36
#define ATT_TILE_W (64 * AS)
#define ATTN_SMEM (6 * ATT_TILE_W * 4)     // 55296 B

__global__ void __launch_bounds__(128)
attn_kernel() {
    extern __shared__ uint32_t sw[];
    uint32_t* Qh = sw;
    uint32_t* Ql = sw + ATT_TILE_W;
    uint32_t* Kh = sw + 2 * ATT_TILE_W;
    uint32_t* Kl = sw + 3 * ATT_TILE_W;
    uint32_t* Vh = sw + 4 * ATT_TILE_W;
    uint32_t* Vl = sw + 5 * ATT_TILE_W;

    const int t = threadIdx.x;
    const int lane = t & 31;
    const int wid = t >> 5;
    const int h = blockIdx.y;
    const int qt = (int)gridDim.x - 1 - (int)blockIdx.x;
    const int qbase = qt * 64;
    const int hw0 = h * 32;                 // word offset of this head

    // ---- Q fill: straight uint2 copies ----
#pragma unroll
    for (int i = 0; i < 8; i++) {
        int idx = i * 128 + t;
        int row = idx >> 4;
        int w2  = (idx & 15) << 1;
        size_t src = (size_t)(qbase + row) * KW + hw0 + w2;
        *(uint2*)&Qh[row * AS + w2] = *(const uint2*)&g_QH[src];
        *(uint2*)&Ql[row * AS + w2] = *(const uint2*)&g_QL[src];
    }
    __syncthreads();

    uint32_t qh[4][4], ql[4][4];
#pragma unroll
    for (int kc = 0; kc < 4; kc++) {
        int base = (wid * 16 + (lane >> 2)) * AS + kc * 8 + (lane & 3);
        qh[kc][0] = Qh[base];
        qh[kc][1] = Qh[base + 8 * AS];
        qh[kc][2] = Qh[base + 4];
        qh[kc][3] = Qh[base + 8 * AS + 4];
        ql[kc][0] = Ql[base];
        ql[kc][1] = Ql[base + 8 * AS];
        ql[kc][2] = Ql[base + 4];
        ql[kc][3] = Ql[base + 8 * AS + 4];
    }

    float o[8][4];
#pragma unroll
    for (int nt = 0; nt < 8; nt++)
#pragma unroll
        for (int r = 0; r < 4; r++) o[nt][r] = 0.f;
    float m0 = -1e30f, m1 = -1e30f, l0 = 0.f, l1 = 0.f;

    for (int kt = 0; kt <= qt; kt++) {
        __syncthreads();
        // K fill
#pragma unroll
        for (int i = 0; i < 8; i++) {
            int idx = i * 128 + t;
            int row = idx >> 4;
            int w2  = (idx & 15) << 1;
            size_t src = (size_t)(kt * 64 + row) * KW + hw0 + w2;
            *(uint2*)&Kh[row * AS + w2] = *(const uint2*)&g_KH[src];
            *(uint2*)&Kl[row * AS + w2] = *(const uint2*)&g_KL[src];
        }
        // V fill (pre-transposed tiles)
        {
            size_t tb = ((size_t)(h * 64 + kt)) << 11;
#pragma unroll
            for (int i = 0; i < 8; i++) {
                int idx = i * 128 + t;
                int d  = idx >> 4;
                int p2 = (idx & 15) << 1;
                *(uint2*)&Vh[d * AS + p2] = *(const uint2*)&g_VH[tb + d * 32 + p2];
                *(uint2*)&Vl[d * AS + p2] = *(const uint2*)&g_VL[tb + d * 32 + p2];
            }
        }
        __syncthreads();

        // S = Q K^T
        float s[8][4];
#pragma unroll
        for (int nt = 0; nt < 8; nt++)
#pragma unroll
            for (int r = 0; r < 4; r++) s[nt][r] = 0.f;

#pragma unroll
        for (int kc = 0; kc < 4; kc++) {
#pragma unroll
            for (int nt = 0; nt < 8; nt++) {
                int kb = (nt * 8 + (lane >> 2)) * AS + kc * 8 + (lane & 3);
                uint32_t bh[2], bl[2];
                bh[0] = Kh[kb]; bh[1] = Kh[kb + 4];
                bl[0] = Kl[kb]; bl[1] = Kl[kb + 4];
                mma_bf16(s[nt], qh[kc], bh);
                mma_bf16(s[nt], ql[kc], bh);
                mma_bf16(s[nt], qh[kc], bl);
            }
        }

        if (kt == qt) {
            int r0 = wid * 16 + (lane >> 2);
            int r1 = r0 + 8;
#pragma unroll
            for (int nt = 0; nt < 8; nt++) {
                int c0 = nt * 8 + 2 * (lane & 3);
                if (c0 > r0)     s[nt][0] = -1e30f;
                if (c0 + 1 > r0) s[nt][1] = -1e30f;
                if (c0 > r1)     s[nt][2] = -1e30f;
                if (c0 + 1 > r1) s[nt][3] = -1e30f;
            }
        }

        float rm0 = -1e30f, rm1 = -1e30f;
#pragma unroll
        for (int nt = 0; nt < 8; nt++) {
            rm0 = fmaxf(rm0, fmaxf(s[nt][0], s[nt][1]));
            rm1 = fmaxf(rm1, fmaxf(s[nt][2], s[nt][3]));
        }
        rm0 = fmaxf(rm0, __shfl_xor_sync(0xffffffffu, rm0, 1));
        rm0 = fmaxf(rm0, __shfl_xor_sync(0xffffffffu, rm0, 2));
        rm1 = fmaxf(rm1, __shfl_xor_sync(0xffffffffu, rm1, 1));
        rm1 = fmaxf(rm1, __shfl_xor_sync(0xffffffffu, rm1, 2));
        float mn0 = fmaxf(m0, rm0), mn1 = fmaxf(m1, rm1);
        float corr0 = __expf(m0 - mn0), corr1 = __expf(m1 - mn1);
        m0 = mn0; m1 = mn1;

        float sum0 = 0.f, sum1 = 0.f;
#pragma unroll
        for (int nt = 0; nt < 8; nt++) {
            s[nt][0] = __expf(s[nt][0] - mn0);
            s[nt][1] = __expf(s[nt][1] - mn0);
            s[nt][2] = __expf(s[nt][2] - mn1);
            s[nt][3] = __expf(s[nt][3] - mn1);
            sum0 += s[nt][0] + s[nt][1];
            sum1 += s[nt][2] + s[nt][3];
        }
        sum0 += __shfl_xor_sync(0xffffffffu, sum0, 1);
        sum0 += __shfl_xor_sync(0xffffffffu, sum0, 2);
        sum1 += __shfl_xor_sync(0xffffffffu, sum1, 1);
        sum1 += __shfl_xor_sync(0xffffffffu, sum1, 2);
        l0 = l0 * corr0 + sum0;
        l1 = l1 * corr1 + sum1;
#pragma unroll
        for (int nt = 0; nt < 8; nt++) {
            o[nt][0] *= corr0; o[nt][1] *= corr0;
            o[nt][2] *= corr1; o[nt][3] *= corr1;
        }

        // O += P V
#pragma unroll
        for (int kc = 0; kc < 4; kc++) {
            const float* sa = s[2 * kc];
            const float* sb = s[2 * kc + 1];
            uint32_t ph[4], pl[4];
            ph[0] = pack2bf(sa[0], sa[1]);
            ph[1] = pack2bf(sa[2], sa[3]);
            ph[2] = pack2bf(sb[0], sb[1]);
            ph[3] = pack2bf(sb[2], sb[3]);
            pl[0] = packlo(sa[0], sa[1]);
            pl[1] = packlo(sa[2], sa[3]);
            pl[2] = packlo(sb[0], sb[1]);
            pl[3] = packlo(sb[2], sb[3]);
#pragma unroll
            for (int nt = 0; nt < 8; nt++) {
                int vb = (nt * 8 + (lane >> 2)) * AS + kc * 8 + (lane & 3);
                uint32_t vh[2], vl[2];
                vh[0] = Vh[vb]; vh[1] = Vh[vb + 4];
                vl[0] = Vl[vb]; vl[1] = Vl[vb + 4];
                mma_bf16(o[nt], ph, vh);
                mma_bf16(o[nt], ph, vl);
                mma_bf16(o[nt], pl, vh);
            }
        }
    }

    // write split output planes
    float inv0 = 1.f / l0, inv1 = 1.f / l1;
    int row = qbase + wid * 16 + (lane >> 2);
#pragma unroll
    for (int nt = 0; nt < 8; nt++) {
        int wc = hw0 + nt * 4 + (lane & 3);
        float a0 = o[nt][0] * inv0, a1 = o[nt][1] * inv0;
        float b0 = o[nt][2] * inv1, b1 = o[nt][3] * inv1;
        g_AtH[(size_t)row * KW + wc]       = pack2bf(a0, a1);
        g_AtL[(size_t)row * KW + wc]       = packlo(a0, a1);
        g_AtH[(size_t)(row + 8) * KW + wc] = pack2bf(b0, b1);
        g_AtL[(size_t)(row + 8) * KW + wc] = packlo(b0, b1);
    }
}

// ---------------------------------------------------------------------------
// LayerNorm
// ---------------------------------------------------------------------------
__global__ void ln_kernel(const float* __restrict__ in,
                          const float* __restrict__ gamma,
                          float* __restrict__ out) {
    __shared__ float sbuf[8];
    const int row = blockIdx.x;
    const int t   = threadIdx.x;

    float4 v = *(const float4*)&in[(size_t)row * DIM + (t << 2)];

    float s = v.x + v.y + v.z + v.w;
#pragma unroll
    for (int o = 16; o; o >>= 1) s += __shfl_xor_sync(0xffffffffu, s, o);
    if ((t & 31) == 0) sbuf[t >> 5] = s;
    __syncthreads();
    float tot = sbuf[0] + sbuf[1] + sbuf[2] + sbuf[3] +
                sbuf[4] + sbuf[5] + sbuf[6] + sbuf[7];
    float mean = tot * (1.f / (float)DIM);
    __syncthreads();

    float dx = v.x - mean, dy = v.y - mean, dz = v.z - mean, dw = v.w - mean;
    float s2 = dx * dx + dy * dy + dz * dz + dw * dw;
#pragma unroll
    for (int o = 16; o; o >>= 1) s2 += __shfl_xor_sync(0xffffffffu, s2, o);
    if ((t & 31) == 0) sbuf[t >> 5] = s2;
    __syncthreads();
    float tot2 = sbuf[0] + sbuf[1] + sbuf[2] + sbuf[3] +
                 sbuf[4] + sbuf[5] + sbuf[6] + sbuf[7];
    float rstd = rsqrtf(tot2 * (1.f / (float)DIM) + 1e-5f);

    float4 g = *(const float4*)&gamma[t << 2];
    float4 r;
    r.x = dx * rstd * g.x;
    r.y = dy * rstd * g.y;
    r.z = dz * rstd * g.z;
    r.w = dw * rstd * g.w;
    *(float4*)&out[(size_t)row * DIM + (t << 2)] = r;
}

// ---------------------------------------------------------------------------
// launch
// ---------------------------------------------------------------------------
extern "C" void kernel_launch(void* const* d_in, const int* in_sizes, int n_in,
                              void* d_out, int out_size) {
    const float* x     = (const float*)d_in[0];
    const float* Wqkv  = (const float*)d_in[1];
    const float* Wo1   = (const float*)d_in[2];
    const float* Wo2   = (const float*)d_in[3];
    const float* gamma = (const float*)d_in[4];
    float* out = (float*)d_out;

    float *qkv, *h2;
    uint32_t *XH, *XL, *AtH, *AtL, *H1H, *H1L;
    uint32_t *WqkvH, *WqkvL, *Wo1H, *Wo1L, *Wo2H, *Wo2L;
    cudaGetSymbolAddress((void**)&qkv, g_qkv);
    cudaGetSymbolAddress((void**)&h2, g_h2);
    cudaGetSymbolAddress((void**)&XH, g_XH);
    cudaGetSymbolAddress((void**)&XL, g_XL);
    cudaGetSymbolAddress((void**)&AtH, g_AtH);
    cudaGetSymbolAddress((void**)&AtL, g_AtL);
    cudaGetSymbolAddress((void**)&H1H, g_H1H);
    cudaGetSymbolAddress((void**)&H1L, g_H1L);
    cudaGetSymbolAddress((void**)&WqkvH, g_WqkvH);
    cudaGetSymbolAddress((void**)&WqkvL, g_WqkvL);
    cudaGetSymbolAddress((void**)&Wo1H, g_Wo1H);
    cudaGetSymbolAddress((void**)&Wo1L, g_Wo1L);
    cudaGetSymbolAddress((void**)&Wo2H, g_Wo2H);
    cudaGetSymbolAddress((void**)&Wo2L, g_Wo2L);

    static bool attr_done = false;
    if (!attr_done) {
        cudaFuncSetAttribute(attn_kernel,
                             cudaFuncAttributeMaxDynamicSharedMemorySize, ATTN_SMEM);
        cudaFuncSetAttribute(gemm_pre<0>,
                             cudaFuncAttributeMaxDynamicSharedMemorySize, GEMM_SMEM);
        cudaFuncSetAttribute(gemm_pre<1>,
                             cudaFuncAttributeMaxDynamicSharedMemorySize, GEMM_SMEM);
        attr_done = true;
    }

    // prep
    split_x_kernel<<<(N_TOK * KW) / 256, 256>>>(x);
    split_w_kernel<<<dim3(QKV_N / 64, DIM / 64), 256>>>(Wqkv, WqkvH, WqkvL, DIM, QKV_N);
    split_w_kernel<<<dim3(DIM / 64, DIM / 64), 256>>>(Wo1, Wo1H, Wo1L, DIM, DIM);
    split_w_kernel<<<dim3(DIM / 64, DIM / 64), 256>>>(Wo2, Wo2H, Wo2L, DIM, DIM);

    // qkv = x @ Wqkv (fp32 out)
    gemm_pre<0><<<dim3(QKV_N / 128, N_TOK / 128), 512, GEMM_SMEM>>>(
        XH, XL, WqkvH, WqkvL, qkv, nullptr, nullptr, N_TOK, QKV_N, DIM);

    // rope+split q/k, transpose+split v
    rope_split_kernel<<<(N_TOK * KW) / 256, 256>>>();
    v_prep_kernel<<<dim3(64, HEADS), 256>>>();

    // attention -> split planes
    attn_kernel<<<dim3(64, HEADS), 128, ATTN_SMEM>>>();

    // h1 = relu(attn @ Wo1) -> split planes
    gemm_pre<1><<<dim3(DIM / 128, N_TOK / 128), 512, GEMM_SMEM>>>(
        AtH, AtL, Wo1H, Wo1L, nullptr, H1H, H1L, N_TOK, DIM, DIM);

    // h2 = h1 @ Wo2 (fp32 out)
    gemm_pre<0><<<dim3(DIM / 128, N_TOK / 128), 512, GEMM_SMEM>>>(
        H1H, H1L, Wo2H, Wo2L, h2, nullptr, nullptr, N_TOK, DIM, DIM);

    // layernorm
    ln_kernel<<<N_TOK, 256>>>(h2, gamma, out);
}

// round 5
// speedup vs baseline: 5.0835x; 1.0919x over previous
#include <cuda_runtime.h>
#include <cuda_bf16.h>
#include <math.h>
#include <stdint.h>

#define N_TOK   4096
#define DIM     1024
#define HEADS   16
#define HD      64
#define QKV_N   3072
#define KW      (DIM / 2)          // 512 packed words per 1024-dim row

// ---------------------------------------------------------------------------
// Scratch
// ---------------------------------------------------------------------------
__device__ float    g_qkv[N_TOK * QKV_N];
__device__ float    g_h2[N_TOK * DIM];
__device__ uint32_t g_XH[N_TOK * KW],  g_XL[N_TOK * KW];
__device__ uint32_t g_QH[N_TOK * KW],  g_QL[N_TOK * KW];
__device__ uint32_t g_KH[N_TOK * KW],  g_KL[N_TOK * KW];
__device__ uint32_t g_VH[HEADS * 64 * 2048], g_VL[HEADS * 64 * 2048];
__device__ uint32_t g_AtH[N_TOK * KW], g_AtL[N_TOK * KW];
__device__ uint32_t g_H1H[N_TOK * KW], g_H1L[N_TOK * KW];
__device__ uint32_t g_WqkvH[QKV_N * KW], g_WqkvL[QKV_N * KW];
__device__ uint32_t g_Wo1H[DIM * KW], g_Wo1L[DIM * KW];
__device__ uint32_t g_Wo2H[DIM * KW], g_Wo2L[DIM * KW];

// ---------------------------------------------------------------------------
// helpers
// ---------------------------------------------------------------------------
__device__ __forceinline__ float bff(float x) {
    return __bfloat162float(__float2bfloat16_rn(x));
}
__device__ __forceinline__ uint32_t pack2bf(float lo, float hi) {
    uint32_t r;
    asm("cvt.rn.bf16x2.f32 %0, %1, %2;" : "=r"(r) : "f"(hi), "f"(lo));
    return r;
}
__device__ __forceinline__ uint32_t packlo(float a, float b) {
    return pack2bf(a - bff(a), b - bff(b));
}
__device__ __forceinline__ void mma_bf16(float* c, const uint32_t* a, const uint32_t* b) {
    asm volatile("mma.sync.aligned.m16n8k16.row.col.f32.bf16.bf16.f32 "
        "{%0,%1,%2,%3}, {%4,%5,%6,%7}, {%8,%9}, {%0,%1,%2,%3};"
        : "+f"(c[0]), "+f"(c[1]), "+f"(c[2]), "+f"(c[3])
        : "r"(a[0]), "r"(a[1]), "r"(a[2]), "r"(a[3]), "r"(b[0]), "r"(b[1]));
}
__device__ __forceinline__ void ldsm4(uint32_t* r, uint32_t addr) {
    asm volatile("ldmatrix.sync.aligned.m8n8.x4.shared.b16 {%0,%1,%2,%3}, [%4];"
        : "=r"(r[0]), "=r"(r[1]), "=r"(r[2]), "=r"(r[3]) : "r"(addr));
}
__device__ __forceinline__ uint32_t smem_u32(const void* p) {
    uint32_t a;
    asm("{ .reg .u64 t; cvta.to.shared.u64 t, %1; cvt.u32.u64 %0, t; }"
        : "=r"(a) : "l"(p));
    return a;
}
#define CP_ASYNC16(dst, src) \
    asm volatile("cp.async.cg.shared.global [%0], [%1], 16;" :: "r"(dst), "l"(src))
#define CP_COMMIT() asm volatile("cp.async.commit_group;")
#define CP_WAIT0()  asm volatile("cp.async.wait_group 0;")
#define CP_WAIT1()  asm volatile("cp.async.wait_group 1;")

// ---------------------------------------------------------------------------
// Prep kernels
// ---------------------------------------------------------------------------
__global__ void split_x_kernel(const float* __restrict__ x) {
    int idx = blockIdx.x * 256 + threadIdx.x;
    float2 v = *(const float2*)&x[(size_t)idx * 2];
    g_XH[idx] = pack2bf(v.x, v.y);
    g_XL[idx] = packlo(v.x, v.y);
}

__global__ void split_w_kernel(const float* __restrict__ W,
                               uint32_t* __restrict__ H, uint32_t* __restrict__ L,
                               int K, int N) {
    __shared__ float S[64][68];
    const int t = threadIdx.x;
    const int k0 = blockIdx.y * 64, n0 = blockIdx.x * 64;
#pragma unroll
    for (int i = 0; i < 4; i++) {
        int slot = i * 256 + t;
        int k = slot >> 4, n4 = (slot & 15) << 2;
        *(float4*)&S[k][n4] = *(const float4*)&W[(size_t)(k0 + k) * N + n0 + n4];
    }
    __syncthreads();
    const int kw = K >> 1;
#pragma unroll
    for (int i = 0; i < 8; i++) {
        int slot = i * 256 + t;
        int n = slot >> 5, kwl = slot & 31;
        float a = S[2 * kwl][n], b = S[2 * kwl + 1][n];
        size_t o = (size_t)(n0 + n) * kw + (k0 >> 1) + kwl;
        H[o] = pack2bf(a, b);
        L[o] = packlo(a, b);
    }
}

__global__ void rope_split_kernel() {
    int idx = blockIdx.x * 256 + threadIdx.x;
    int row  = idx >> 9;
    int hw   = idx & 511;
    int head = hw >> 5;
    int w    = hw & 31;
    int d0   = w * 2;
    int i0   = d0 & 31;

    float invf0 = powf(10000.f, -(float)i0 * (1.f / 32.f));
    float invf1 = powf(10000.f, -(float)(i0 + 1) * (1.f / 32.f));
    float s0, c0, s1, c1;
    sincosf((float)row * invf0, &s0, &c0);
    sincosf((float)row * invf1, &s1, &c1);

    bool half = (d0 < 32);
    size_t base = (size_t)row * QKV_N + head * HD + d0;
    size_t pb   = half ? base + 32 : base - 32;

    float q0 = g_qkv[base],       q1 = g_qkv[base + 1];
    float qp0 = g_qkv[pb],        qp1 = g_qkv[pb + 1];
    float k0 = g_qkv[base + DIM], k1 = g_qkv[base + DIM + 1];
    float kp0 = g_qkv[pb + DIM],  kp1 = g_qkv[pb + DIM + 1];

    float oq0, oq1, ok0, ok1;
    if (half) {
        oq0 = q0 * c0 - qp0 * s0;  oq1 = q1 * c1 - qp1 * s1;
        ok0 = k0 * c0 - kp0 * s0;  ok1 = k1 * c1 - kp1 * s1;
    } else {
        oq0 = q0 * c0 + qp0 * s0;  oq1 = q1 * c1 + qp1 * s1;
        ok0 = k0 * c0 + kp0 * s0;  ok1 = k1 * c1 + kp1 * s1;
    }
    oq0 *= 0.125f; oq1 *= 0.125f;

    g_QH[idx] = pack2bf(oq0, oq1);
    g_QL[idx] = packlo(oq0, oq1);
    g_KH[idx] = pack2bf(ok0, ok1);
    g_KL[idx] = packlo(ok0, ok1);
}

__global__ void v_prep_kernel() {
    __shared__ float S[64][68];
    const int t = threadIdx.x;
    const int kt = blockIdx.x, h = blockIdx.y;
#pragma unroll
    for (int i = 0; i < 4; i++) {
        int slot = i * 256 + t;
        int r = slot >> 4, c4 = (slot & 15) << 2;
        *(float4*)&S[r][c4] =
            *(const float4*)&g_qkv[(size_t)(kt * 64 + r) * QKV_N + 2 * DIM + h * HD + c4];
    }
    __syncthreads();
    size_t tb = ((size_t)(h * 64 + kt)) << 11;
#pragma unroll
    for (int i = 0; i < 8; i++) {
        int slot = i * 256 + t;
        int d = slot >> 5, p = slot & 31;
        float a = S[2 * p][d], b = S[2 * p + 1][d];
        g_VH[tb + slot] = pack2bf(a, b);
        g_VL[tb + slot] = packlo(a, b);
    }
}

// ---------------------------------------------------------------------------
// GEMM (pre-split operands, ldmatrix feeds, cp.async double buffer)
// ---------------------------------------------------------------------------
#define GS 20
#define GEMM_BUF_W (4 * 128 * GS)
#define GEMM_SMEM  (2 * GEMM_BUF_W * 4)

template <int MODE>
__global__ void __launch_bounds__(512)
gemm_pre(const uint32_t* __restrict__ AH, const uint32_t* __restrict__ AL,
         const uint32_t* __restrict__ BH, const uint32_t* __restrict__ BL,
         float* __restrict__ Cf, uint32_t* __restrict__ CH, uint32_t* __restrict__ CL,
         int M, int N, int K) {
    extern __shared__ uint32_t sw[];
    const int kw = K >> 1;
    const int t = threadIdx.x;
    const int lane = t & 31;
    const int wid = t >> 5;
    const int wm = wid & 3;
    const int wn = wid >> 2;
    const int bm = blockIdx.y * 128;
    const int bn = blockIdx.x * 128;
    const uint32_t sb = smem_u32(sw);

    const int frow = t >> 2;
    const int fw4  = (t & 3) << 2;
    const uint32_t* sAH = &AH[(size_t)(bm + frow) * kw + fw4];
    const uint32_t* sAL = &AL[(size_t)(bm + frow) * kw + fw4];
    const uint32_t* sBH = &BH[(size_t)(bn + frow) * kw + fw4];
    const uint32_t* sBL = &BL[(size_t)(bn + frow) * kw + fw4];
    const uint32_t dbase = sb + (frow * GS + fw4) * 4;

    auto issue = [&](int c) {
        uint32_t d = dbase + ((c & 1) * GEMM_BUF_W) * 4;
        int go = c * 16;
        CP_ASYNC16(d,            sAH + go);
        CP_ASYNC16(d + 2560 * 4, sAL + go);
        CP_ASYNC16(d + 5120 * 4, sBH + go);
        CP_ASYNC16(d + 7680 * 4, sBL + go);
    };

    // ldmatrix per-lane base offsets (bytes, relative to buffer start)
    const uint32_t aw = ((wm * 32 + (lane & 15)) * GS + (lane >> 4) * 4) * 4;
    const int g = lane >> 3;
    const uint32_t bw = ((wn * 32 + (g >> 1) * 8 + (lane & 7)) * GS + (g & 1) * 4) * 4;

    float acc[2][4][4];
#pragma unroll
    for (int i = 0; i < 2; i++)
#pragma unroll
        for (int j = 0; j < 4; j++)
#pragma unroll
            for (int r = 0; r < 4; r++) acc[i][j][r] = 0.f;

    const int nch = K / 32;
    issue(0); CP_COMMIT();

    for (int c = 0; c < nch; c++) {
        if (c + 1 < nch) { issue(c + 1); CP_COMMIT(); CP_WAIT1(); }
        else             { CP_WAIT0(); }
        __syncthreads();

        const uint32_t bufb = sb + ((c & 1) * GEMM_BUF_W) * 4;

#pragma unroll
        for (int ks = 0; ks < 2; ks++) {
            uint32_t ah[2][4], al[2][4], bh[2][4], bl[2][4];
#pragma unroll
            for (int mt = 0; mt < 2; mt++) {
                uint32_t ad = bufb + aw + (mt * 16 * GS + ks * 8) * 4;
                ldsm4(ah[mt], ad);
                ldsm4(al[mt], ad + 2560 * 4);
            }
#pragma unroll
            for (int p = 0; p < 2; p++) {
                uint32_t bd = bufb + bw + (p * 16 * GS + ks * 8) * 4;
                ldsm4(bh[p], bd + 5120 * 4);
                ldsm4(bl[p], bd + 7680 * 4);
            }
#pragma unroll
            for (int mt = 0; mt < 2; mt++)
#pragma unroll
                for (int nt = 0; nt < 4; nt++) {
                    const uint32_t* bhp = &bh[nt >> 1][(nt & 1) * 2];
                    const uint32_t* blp = &bl[nt >> 1][(nt & 1) * 2];
                    mma_bf16(acc[mt][nt], ah[mt], bhp);
                    mma_bf16(acc[mt][nt], al[mt], bhp);
                    mma_bf16(acc[mt][nt], ah[mt], blp);
                }
        }
        __syncthreads();
    }

#pragma unroll
    for (int mt = 0; mt < 2; mt++)
#pragma unroll
        for (int nt = 0; nt < 4; nt++) {
            int row = bm + wm * 32 + mt * 16 + (lane >> 2);
            int col = bn + wn * 32 + nt * 8 + 2 * (lane & 3);
            float v0 = acc[mt][nt][0], v1 = acc[mt][nt][1];
            float v2 = acc[mt][nt][2], v3 = acc[mt][nt][3];
            if (MODE == 1) {
                v0 = fmaxf(v0, 0.f); v1 = fmaxf(v1, 0.f);
                v2 = fmaxf(v2, 0.f); v3 = fmaxf(v3, 0.f);
                int wc = col >> 1;
                CH[(size_t)row * (N >> 1) + wc]       = pack2bf(v0, v1);
                CL[(size_t)row * (N >> 1) + wc]       = packlo(v0, v1);
                CH[(size_t)(row + 8) * (N >> 1) + wc] = pack2bf(v2, v3);
                CL[(size_t)(row + 8) * (N >> 1) + wc] = packlo(v2, v3);
            } else {
                *(float2*)&Cf[(size_t)row * N + col]       = make_float2(v0, v1);
                *(float2*)&Cf[(size_t)(row + 8) * N + col] = make_float2(v2, v3);
            }
        }
}

// ---------------------------------------------------------------------------
// Flash attention: ldmatrix + cp.async double-buffered K/V tiles.
// 4 warps, 64 q rows, one head.
// Per buffer (words): Kh[64*36] @0, Kl @2304, Vh @4608, Vl @6912 -> 9216
// ---------------------------------------------------------------------------
#define AS 36
#define BUFW 9216
#define ATTN_SMEM (2 * BUFW * 4)     // 73728 B

__global__ void __launch_bounds__(128)
attn_kernel() {
    extern __shared__ uint32_t sw[];
    const uint32_t sb = smem_u32(sw);

    const int t = threadIdx.x;
    const int lane = t & 31;
    const int wid = t >> 5;
    const int h = blockIdx.y;
    const int qt = (int)gridDim.x - 1 - (int)blockIdx.x;
    const int qbase = qt * 64;
    const int hw0 = h * 32;

    // ---- stage Q into buf0 (Kh/Kl regions), extract frags, then reuse ----
#pragma unroll
    for (int i = 0; i < 8; i++) {
        int idx = i * 128 + t;
        int row = idx >> 4;
        int w2  = (idx & 15) << 1;
        size_t src = (size_t)(qbase + row) * KW + hw0 + w2;
        *(uint2*)&sw[row * AS + w2]        = *(const uint2*)&g_QH[src];
        *(uint2*)&sw[2304 + row * AS + w2] = *(const uint2*)&g_QL[src];
    }
    __syncthreads();

    uint32_t qh[4][4], ql[4][4];
    {
        uint32_t qa = sb + ((wid * 16 + (lane & 15)) * AS + (lane >> 4) * 4) * 4;
#pragma unroll
        for (int kc = 0; kc < 4; kc++) {
            ldsm4(qh[kc], qa + kc * 32);
            ldsm4(ql[kc], qa + 2304 * 4 + kc * 32);
        }
    }
    __syncthreads();

    // ldmatrix per-lane base for K/V B-frags (bytes, rel. to array start)
    const int g = lane >> 3;
    const uint32_t bw = (((g >> 1) * 8 + (lane & 7)) * AS + (g & 1) * 4) * 4;

    auto issueKV = [&](int kt, int b) {
        uint32_t dstb = sb + (b * BUFW) * 4;
        size_t krow = (size_t)kt * 64;
        size_t tb = ((size_t)(h * 64 + kt)) << 11;
#pragma unroll
        for (int j = 0; j < 4; j++) {
            int idx = j * 128 + t;
            int row = idx >> 3;
            int seg = (idx & 7) << 2;
            uint32_t d0 = dstb + (row * AS + seg) * 4;
            CP_ASYNC16(d0,            &g_KH[(krow + row) * KW + hw0 + seg]);
            CP_ASYNC16(d0 + 2304 * 4, &g_KL[(krow + row) * KW + hw0 + seg]);
            CP_ASYNC16(d0 + 4608 * 4, &g_VH[tb + row * 32 + seg]);
            CP_ASYNC16(d0 + 6912 * 4, &g_VL[tb + row * 32 + seg]);
        }
    };

    float o[8][4];
#pragma unroll
    for (int nt = 0; nt < 8; nt++)
#pragma unroll
        for (int r = 0; r < 4; r++) o[nt][r] = 0.f;
    float m0 = -1e30f, m1 = -1e30f, l0 = 0.f, l1 = 0.f;

    issueKV(0, 0); CP_COMMIT();

    for (int kt = 0; kt <= qt; kt++) {
        if (kt < qt) { issueKV(kt + 1, (kt + 1) & 1); CP_COMMIT(); CP_WAIT1(); }
        else         { CP_WAIT0(); }
        __syncthreads();

        const uint32_t bufb = sb + ((kt & 1) * BUFW) * 4;

        // ---- S = Q K^T ----
        float s[8][4];
#pragma unroll
        for (int nt = 0; nt < 8; nt++)
#pragma unroll
            for (int r = 0; r < 4; r++) s[nt][r] = 0.f;

#pragma unroll
        for (int kc = 0; kc < 4; kc++) {
            uint32_t kh4[4][4], kl4[4][4];
#pragma unroll
            for (int p = 0; p < 4; p++) {
                uint32_t kd = bufb + bw + (p * 16 * AS + kc * 8) * 4;
                ldsm4(kh4[p], kd);
                ldsm4(kl4[p], kd + 2304 * 4);
            }
#pragma unroll
            for (int nt = 0; nt < 8; nt++) {
                const uint32_t* bh = &kh4[nt >> 1][(nt & 1) * 2];
                const uint32_t* bl = &kl4[nt >> 1][(nt & 1) * 2];
                mma_bf16(s[nt], qh[kc], bh);
                mma_bf16(s[nt], ql[kc], bh);
                mma_bf16(s[nt], qh[kc], bl);
            }
        }

        if (kt == qt) {
            int r0 = wid * 16 + (lane >> 2);
            int r1 = r0 + 8;
#pragma unroll
            for (int nt = 0; nt < 8; nt++) {
                int c0 = nt * 8 + 2 * (lane & 3);
                if (c0 > r0)     s[nt][0] = -1e30f;
                if (c0 + 1 > r0) s[nt][1] = -1e30f;
                if (c0 > r1)     s[nt][2] = -1e30f;
                if (c0 + 1 > r1) s[nt][3] = -1e30f;
            }
        }

        // ---- online softmax ----
        float rm0 = -1e30f, rm1 = -1e30f;
#pragma unroll
        for (int nt = 0; nt < 8; nt++) {
            rm0 = fmaxf(rm0, fmaxf(s[nt][0], s[nt][1]));
            rm1 = fmaxf(rm1, fmaxf(s[nt][2], s[nt][3]));
        }
        rm0 = fmaxf(rm0, __shfl_xor_sync(0xffffffffu, rm0, 1));
        rm0 = fmaxf(rm0, __shfl_xor_sync(0xffffffffu, rm0, 2));
        rm1 = fmaxf(rm1, __shfl_xor_sync(0xffffffffu, rm1, 1));
        rm1 = fmaxf(rm1, __shfl_xor_sync(0xffffffffu, rm1, 2));
        float mn0 = fmaxf(m0, rm0), mn1 = fmaxf(m1, rm1);
        float corr0 = __expf(m0 - mn0), corr1 = __expf(m1 - mn1);
        m0 = mn0; m1 = mn1;

        float sum0 = 0.f, sum1 = 0.f;
#pragma unroll
        for (int nt = 0; nt < 8; nt++) {
            s[nt][0] = __expf(s[nt][0] - mn0);
            s[nt][1] = __expf(s[nt][1] - mn0);
            s[nt][2] = __expf(s[nt][2] - mn1);
            s[nt][3] = __expf(s[nt][3] - mn1);
            sum0 += s[nt][0] + s[nt][1];
            sum1 += s[nt][2] + s[nt][3];
        }
        sum0 += __shfl_xor_sync(0xffffffffu, sum0, 1);
        sum0 += __shfl_xor_sync(0xffffffffu, sum0, 2);
        sum1 += __shfl_xor_sync(0xffffffffu, sum1, 1);
        sum1 += __shfl_xor_sync(0xffffffffu, sum1, 2);
        l0 = l0 * corr0 + sum0;
        l1 = l1 * corr1 + sum1;
#pragma unroll
        for (int nt = 0; nt < 8; nt++) {
            o[nt][0] *= corr0; o[nt][1] *= corr0;
            o[nt][2] *= corr1; o[nt][3] *= corr1;
        }

        // ---- O += P V ----
#pragma unroll
        for (int kc = 0; kc < 4; kc++) {
            const float* sa = s[2 * kc];
            const float* sbv = s[2 * kc + 1];
            uint32_t ph[4], pl[4];
            ph[0] = pack2bf(sa[0], sa[1]);
            ph[1] = pack2bf(sa[2], sa[3]);
            ph[2] = pack2bf(sbv[0], sbv[1]);
            ph[3] = pack2bf(sbv[2], sbv[3]);
            pl[0] = packlo(sa[0], sa[1]);
            pl[1] = packlo(sa[2], sa[3]);
            pl[2] = packlo(sbv[0], sbv[1]);
            pl[3] = packlo(sbv[2], sbv[3]);

            uint32_t vh4[4][4], vl4[4][4];
#pragma unroll
            for (int p = 0; p < 4; p++) {
                uint32_t vd = bufb + bw + (p * 16 * AS + kc * 8) * 4;
                ldsm4(vh4[p], vd + 4608 * 4);
                ldsm4(vl4[p], vd + 6912 * 4);
            }
#pragma unroll
            for (int nt = 0; nt < 8; nt++) {
                const uint32_t* vh = &vh4[nt >> 1][(nt & 1) * 2];
                const uint32_t* vl = &vl4[nt >> 1][(nt & 1) * 2];
                mma_bf16(o[nt], ph, vh);
                mma_bf16(o[nt], ph, vl);
                mma_bf16(o[nt], pl, vh);
            }
        }
        __syncthreads();
    }

    // ---- write split output planes ----
    float inv0 = 1.f / l0, inv1 = 1.f / l1;
    int row = qbase + wid * 16 + (lane >> 2);
#pragma unroll
    for (int nt = 0; nt < 8; nt++) {
        int wc = hw0 + nt * 4 + (lane & 3);
        float a0 = o[nt][0] * inv0, a1 = o[nt][1] * inv0;
        float b0 = o[nt][2] * inv1, b1 = o[nt][3] * inv1;
        g_AtH[(size_t)row * KW + wc]       = pack2bf(a0, a1);
        g_AtL[(size_t)row * KW + wc]       = packlo(a0, a1);
        g_AtH[(size_t)(row + 8) * KW + wc] = pack2bf(b0, b1);
        g_AtL[(size_t)(row + 8) * KW + wc] = packlo(b0, b1);
    }
}

// ---------------------------------------------------------------------------
// LayerNorm
// ---------------------------------------------------------------------------
__global__ void ln_kernel(const float* __restrict__ in,
                          const float* __restrict__ gamma,
                          float* __restrict__ out) {
    __shared__ float sbuf[8];
    const int row = blockIdx.x;
    const int t   = threadIdx.x;

    float4 v = *(const float4*)&in[(size_t)row * DIM + (t << 2)];

    float s = v.x + v.y + v.z + v.w;
#pragma unroll
    for (int o = 16; o; o >>= 1) s += __shfl_xor_sync(0xffffffffu, s, o);
    if ((t & 31) == 0) sbuf[t >> 5] = s;
    __syncthreads();
    float tot = sbuf[0] + sbuf[1] + sbuf[2] + sbuf[3] +
                sbuf[4] + sbuf[5] + sbuf[6] + sbuf[7];
    float mean = tot * (1.f / (float)DIM);
    __syncthreads();

    float dx = v.x - mean, dy = v.y - mean, dz = v.z - mean, dw = v.w - mean;
    float s2 = dx * dx + dy * dy + dz * dz + dw * dw;
#pragma unroll
    for (int o = 16; o; o >>= 1) s2 += __shfl_xor_sync(0xffffffffu, s2, o);
    if ((t & 31) == 0) sbuf[t >> 5] = s2;
    __syncthreads();
    float tot2 = sbuf[0] + sbuf[1] + sbuf[2] + sbuf[3] +
                 sbuf[4] + sbuf[5] + sbuf[6] + sbuf[7];
    float rstd = rsqrtf(tot2 * (1.f / (float)DIM) + 1e-5f);

    float4 gm = *(const float4*)&gamma[t << 2];
    float4 r;
    r.x = dx * rstd * gm.x;
    r.y = dy * rstd * gm.y;
    r.z = dz * rstd * gm.z;
    r.w = dw * rstd * gm.w;
    *(float4*)&out[(size_t)row * DIM + (t << 2)] = r;
}

// ---------------------------------------------------------------------------
// launch
// ---------------------------------------------------------------------------
extern "C" void kernel_launch(void* const* d_in, const int* in_sizes, int n_in,
                              void* d_out, int out_size) {
    const float* x     = (const float*)d_in[0];
    const float* Wqkv  = (const float*)d_in[1];
    const float* Wo1   = (const float*)d_in[2];
    const float* Wo2   = (const float*)d_in[3];
    const float* gamma = (const float*)d_in[4];
    float* out = (float*)d_out;

    float *qkv, *h2;
    uint32_t *XH, *XL, *AtH, *AtL, *H1H, *H1L;
    uint32_t *WqkvH, *WqkvL, *Wo1H, *Wo1L, *Wo2H, *Wo2L;
    cudaGetSymbolAddress((void**)&qkv, g_qkv);
    cudaGetSymbolAddress((void**)&h2, g_h2);
    cudaGetSymbolAddress((void**)&XH, g_XH);
    cudaGetSymbolAddress((void**)&XL, g_XL);
    cudaGetSymbolAddress((void**)&AtH, g_AtH);
    cudaGetSymbolAddress((void**)&AtL, g_AtL);
    cudaGetSymbolAddress((void**)&H1H, g_H1H);
    cudaGetSymbolAddress((void**)&H1L, g_H1L);
    cudaGetSymbolAddress((void**)&WqkvH, g_WqkvH);
    cudaGetSymbolAddress((void**)&WqkvL, g_WqkvL);
    cudaGetSymbolAddress((void**)&Wo1H, g_Wo1H);
    cudaGetSymbolAddress((void**)&Wo1L, g_Wo1L);
    cudaGetSymbolAddress((void**)&Wo2H, g_Wo2H);
    cudaGetSymbolAddress((void**)&Wo2L, g_Wo2L);

    static bool attr_done = false;
    if (!attr_done) {
        cudaFuncSetAttribute(attn_kernel,
                             cudaFuncAttributeMaxDynamicSharedMemorySize, ATTN_SMEM);
        cudaFuncSetAttribute(gemm_pre<0>,
                             cudaFuncAttributeMaxDynamicSharedMemorySize, GEMM_SMEM);
        cudaFuncSetAttribute(gemm_pre<1>,
                             cudaFuncAttributeMaxDynamicSharedMemorySize, GEMM_SMEM);
        attr_done = true;
    }

    split_x_kernel<<<(N_TOK * KW) / 256, 256>>>(x);
    split_w_kernel<<<dim3(QKV_N / 64, DIM / 64), 256>>>(Wqkv, WqkvH, WqkvL, DIM, QKV_N);
    split_w_kernel<<<dim3(DIM / 64, DIM / 64), 256>>>(Wo1, Wo1H, Wo1L, DIM, DIM);
    split_w_kernel<<<dim3(DIM / 64, DIM / 64), 256>>>(Wo2, Wo2H, Wo2L, DIM, DIM);

    gemm_pre<0><<<dim3(QKV_N / 128, N_TOK / 128), 512, GEMM_SMEM>>>(
        XH, XL, WqkvH, WqkvL, qkv, nullptr, nullptr, N_TOK, QKV_N, DIM);

    rope_split_kernel<<<(N_TOK * KW) / 256, 256>>>();
    v_prep_kernel<<<dim3(64, HEADS), 256>>>();

    attn_kernel<<<dim3(64, HEADS), 128, ATTN_SMEM>>>();

    gemm_pre<1><<<dim3(DIM / 128, N_TOK / 128), 512, GEMM_SMEM>>>(
        AtH, AtL, Wo1H, Wo1L, nullptr, H1H, H1L, N_TOK, DIM, DIM);

    gemm_pre<0><<<dim3(DIM / 128, N_TOK / 128), 512, GEMM_SMEM>>>(
        H1H, H1L, Wo2H, Wo2L, h2, nullptr, nullptr, N_TOK, DIM, DIM);

    ln_kernel<<<N_TOK, 256>>>(h2, gamma, out);
}

// round 6
// speedup vs baseline: 6.8114x; 1.3399x over previous
#include <cuda_runtime.h>
#include <cuda_bf16.h>
#include <cuda_fp16.h>
#include <math.h>
#include <stdint.h>

#define N_TOK   4096
#define DIM     1024
#define HEADS   16
#define HD      64
#define QKV_N   3072
#define KW      (DIM / 2)          // 512 packed words per 1024-dim row

// ---------------------------------------------------------------------------
// Scratch
// ---------------------------------------------------------------------------
__device__ float    g_qkv[N_TOK * QKV_N];
__device__ float    g_h2[N_TOK * DIM];
__device__ uint32_t g_XH[N_TOK * KW],  g_XL[N_TOK * KW];     // x split (fp16)
__device__ uint32_t g_QH[N_TOK * KW],  g_QL[N_TOK * KW];     // q split (fp16)
__device__ uint32_t g_KP[N_TOK * KW];                        // k single fp16
__device__ uint32_t g_VP[HEADS * 64 * 2048];                 // v single fp16 (transposed tiles)
__device__ uint32_t g_AtH[N_TOK * KW], g_AtL[N_TOK * KW];
__device__ uint32_t g_H1H[N_TOK * KW], g_H1L[N_TOK * KW];
__device__ uint32_t g_WqkvP[QKV_N * KW];
__device__ uint32_t g_Wo1P[DIM * KW];
__device__ uint32_t g_Wo2P[DIM * KW];

// ---------------------------------------------------------------------------
// helpers
// ---------------------------------------------------------------------------
__device__ __forceinline__ float hff(float x) {              // fp16 round trip
    return __half2float(__float2half_rn(x));
}
__device__ __forceinline__ uint32_t pack2h(float lo, float hi) {  // lo->bits[0:16)
    uint32_t r;
    asm("cvt.rn.f16x2.f32 %0, %1, %2;" : "=r"(r) : "f"(hi), "f"(lo));
    return r;
}
__device__ __forceinline__ uint32_t packlo16(float a, float b) {  // residuals
    return pack2h(a - hff(a), b - hff(b));
}
__device__ __forceinline__ void mma_fp16(float* c, const uint32_t* a, const uint32_t* b) {
    asm volatile("mma.sync.aligned.m16n8k16.row.col.f32.f16.f16.f32 "
        "{%0,%1,%2,%3}, {%4,%5,%6,%7}, {%8,%9}, {%0,%1,%2,%3};"
        : "+f"(c[0]), "+f"(c[1]), "+f"(c[2]), "+f"(c[3])
        : "r"(a[0]), "r"(a[1]), "r"(a[2]), "r"(a[3]), "r"(b[0]), "r"(b[1]));
}
__device__ __forceinline__ void ldsm4(uint32_t* r, uint32_t addr) {
    asm volatile("ldmatrix.sync.aligned.m8n8.x4.shared.b16 {%0,%1,%2,%3}, [%4];"
        : "=r"(r[0]), "=r"(r[1]), "=r"(r[2]), "=r"(r[3]) : "r"(addr));
}
__device__ __forceinline__ uint32_t smem_u32(const void* p) {
    uint32_t a;
    asm("{ .reg .u64 t; cvta.to.shared.u64 t, %1; cvt.u32.u64 %0, t; }"
        : "=r"(a) : "l"(p));
    return a;
}
#define CP_ASYNC16(dst, src) \
    asm volatile("cp.async.cg.shared.global [%0], [%1], 16;" :: "r"(dst), "l"(src))
#define CP_COMMIT() asm volatile("cp.async.commit_group;")
#define CP_WAIT0()  asm volatile("cp.async.wait_group 0;")
#define CP_WAIT1()  asm volatile("cp.async.wait_group 1;")

// ---------------------------------------------------------------------------
// Prep kernels
// ---------------------------------------------------------------------------
__global__ void split_x_kernel(const float* __restrict__ x) {
    int idx = blockIdx.x * 256 + threadIdx.x;
    float2 v = *(const float2*)&x[(size_t)idx * 2];
    g_XH[idx] = pack2h(v.x, v.y);
    g_XL[idx] = packlo16(v.x, v.y);
}

// W[K][N] -> single fp16 plane [N][K/2]
__global__ void split_w_kernel(const float* __restrict__ W,
                               uint32_t* __restrict__ P, int K, int N) {
    __shared__ float S[64][68];
    const int t = threadIdx.x;
    const int k0 = blockIdx.y * 64, n0 = blockIdx.x * 64;
#pragma unroll
    for (int i = 0; i < 4; i++) {
        int slot = i * 256 + t;
        int k = slot >> 4, n4 = (slot & 15) << 2;
        *(float4*)&S[k][n4] = *(const float4*)&W[(size_t)(k0 + k) * N + n0 + n4];
    }
    __syncthreads();
    const int kw = K >> 1;
#pragma unroll
    for (int i = 0; i < 8; i++) {
        int slot = i * 256 + t;
        int n = slot >> 5, kwl = slot & 31;
        P[(size_t)(n0 + n) * kw + (k0 >> 1) + kwl] = pack2h(S[2 * kwl][n], S[2 * kwl + 1][n]);
    }
}

__global__ void rope_split_kernel() {
    int idx = blockIdx.x * 256 + threadIdx.x;
    int row  = idx >> 9;
    int hw   = idx & 511;
    int head = hw >> 5;
    int w    = hw & 31;
    int d0   = w * 2;
    int i0   = d0 & 31;

    float invf0 = powf(10000.f, -(float)i0 * (1.f / 32.f));
    float invf1 = powf(10000.f, -(float)(i0 + 1) * (1.f / 32.f));
    float s0, c0, s1, c1;
    sincosf((float)row * invf0, &s0, &c0);
    sincosf((float)row * invf1, &s1, &c1);

    bool half = (d0 < 32);
    size_t base = (size_t)row * QKV_N + head * HD + d0;
    size_t pb   = half ? base + 32 : base - 32;

    float q0 = g_qkv[base],       q1 = g_qkv[base + 1];
    float qp0 = g_qkv[pb],        qp1 = g_qkv[pb + 1];
    float k0 = g_qkv[base + DIM], k1 = g_qkv[base + DIM + 1];
    float kp0 = g_qkv[pb + DIM],  kp1 = g_qkv[pb + DIM + 1];

    float oq0, oq1, ok0, ok1;
    if (half) {
        oq0 = q0 * c0 - qp0 * s0;  oq1 = q1 * c1 - qp1 * s1;
        ok0 = k0 * c0 - kp0 * s0;  ok1 = k1 * c1 - kp1 * s1;
    } else {
        oq0 = q0 * c0 + qp0 * s0;  oq1 = q1 * c1 + qp1 * s1;
        ok0 = k0 * c0 + kp0 * s0;  ok1 = k1 * c1 + kp1 * s1;
    }
    oq0 *= 0.125f; oq1 *= 0.125f;

    g_QH[idx] = pack2h(oq0, oq1);
    g_QL[idx] = packlo16(oq0, oq1);
    g_KP[idx] = pack2h(ok0, ok1);
}

__global__ void v_prep_kernel() {
    __shared__ float S[64][68];
    const int t = threadIdx.x;
    const int kt = blockIdx.x, h = blockIdx.y;
#pragma unroll
    for (int i = 0; i < 4; i++) {
        int slot = i * 256 + t;
        int r = slot >> 4, c4 = (slot & 15) << 2;
        *(float4*)&S[r][c4] =
            *(const float4*)&g_qkv[(size_t)(kt * 64 + r) * QKV_N + 2 * DIM + h * HD + c4];
    }
    __syncthreads();
    size_t tb = ((size_t)(h * 64 + kt)) << 11;
#pragma unroll
    for (int i = 0; i < 8; i++) {
        int slot = i * 256 + t;
        int d = slot >> 5, p = slot & 31;
        g_VP[tb + slot] = pack2h(S[2 * p][d], S[2 * p + 1][d]);
    }
}

// ---------------------------------------------------------------------------
// GEMM: A split (AH,AL fp16) x B single (BP fp16), 2-term.
// Smem/buffer (words): Ah @0, Al @2560, B @5120 -> 7680 (30 KB), 2 buffers.
// ---------------------------------------------------------------------------
#define GS 20
#define GEMM_BUF_W (3 * 128 * GS)               // 7680 words
#define GEMM_SMEM  (2 * GEMM_BUF_W * 4)         // 61440 B

template <int MODE>
__global__ void __launch_bounds__(512)
gemm_pre(const uint32_t* __restrict__ AH, const uint32_t* __restrict__ AL,
         const uint32_t* __restrict__ BP,
         float* __restrict__ Cf, uint32_t* __restrict__ CH, uint32_t* __restrict__ CL,
         int M, int N, int K) {
    extern __shared__ uint32_t sw[];
    const int kw = K >> 1;
    const int t = threadIdx.x;
    const int lane = t & 31;
    const int wid = t >> 5;
    const int wm = wid & 3;
    const int wn = wid >> 2;
    const int bm = blockIdx.y * 128;
    const int bn = blockIdx.x * 128;
    const uint32_t sb = smem_u32(sw);

    const int frow = t >> 2;
    const int fw4  = (t & 3) << 2;
    const uint32_t* sAH = &AH[(size_t)(bm + frow) * kw + fw4];
    const uint32_t* sAL = &AL[(size_t)(bm + frow) * kw + fw4];
    const uint32_t* sBP = &BP[(size_t)(bn + frow) * kw + fw4];
    const uint32_t dbase = sb + (frow * GS + fw4) * 4;

    auto issue = [&](int c) {
        uint32_t d = dbase + ((c & 1) * GEMM_BUF_W) * 4;
        int go = c * 16;
        CP_ASYNC16(d,            sAH + go);
        CP_ASYNC16(d + 2560 * 4, sAL + go);
        CP_ASYNC16(d + 5120 * 4, sBP + go);
    };

    const uint32_t aw = ((wm * 32 + (lane & 15)) * GS + (lane >> 4) * 4) * 4;
    const int g = lane >> 3;
    const uint32_t bw = ((wn * 32 + (g >> 1) * 8 + (lane & 7)) * GS + (g & 1) * 4) * 4;

    float acc[2][4][4];
#pragma unroll
    for (int i = 0; i < 2; i++)
#pragma unroll
        for (int j = 0; j < 4; j++)
#pragma unroll
            for (int r = 0; r < 4; r++) acc[i][j][r] = 0.f;

    const int nch = K / 32;
    issue(0); CP_COMMIT();

    for (int c = 0; c < nch; c++) {
        if (c + 1 < nch) { issue(c + 1); CP_COMMIT(); CP_WAIT1(); }
        else             { CP_WAIT0(); }
        __syncthreads();

        const uint32_t bufb = sb + ((c & 1) * GEMM_BUF_W) * 4;

#pragma unroll
        for (int ks = 0; ks < 2; ks++) {
            uint32_t ah[2][4], al[2][4], bp[2][4];
#pragma unroll
            for (int mt = 0; mt < 2; mt++) {
                uint32_t ad = bufb + aw + (mt * 16 * GS + ks * 8) * 4;
                ldsm4(ah[mt], ad);
                ldsm4(al[mt], ad + 2560 * 4);
            }
#pragma unroll
            for (int p = 0; p < 2; p++) {
                uint32_t bd = bufb + bw + (p * 16 * GS + ks * 8) * 4;
                ldsm4(bp[p], bd + 5120 * 4);
            }
#pragma unroll
            for (int mt = 0; mt < 2; mt++)
#pragma unroll
                for (int nt = 0; nt < 4; nt++) {
                    const uint32_t* bpp = &bp[nt >> 1][(nt & 1) * 2];
                    mma_fp16(acc[mt][nt], ah[mt], bpp);
                    mma_fp16(acc[mt][nt], al[mt], bpp);
                }
        }
        __syncthreads();
    }

#pragma unroll
    for (int mt = 0; mt < 2; mt++)
#pragma unroll
        for (int nt = 0; nt < 4; nt++) {
            int row = bm + wm * 32 + mt * 16 + (lane >> 2);
            int col = bn + wn * 32 + nt * 8 + 2 * (lane & 3);
            float v0 = acc[mt][nt][0], v1 = acc[mt][nt][1];
            float v2 = acc[mt][nt][2], v3 = acc[mt][nt][3];
            if (MODE == 1) {
                v0 = fmaxf(v0, 0.f); v1 = fmaxf(v1, 0.f);
                v2 = fmaxf(v2, 0.f); v3 = fmaxf(v3, 0.f);
                int wc = col >> 1;
                CH[(size_t)row * (N >> 1) + wc]       = pack2h(v0, v1);
                CL[(size_t)row * (N >> 1) + wc]       = packlo16(v0, v1);
                CH[(size_t)(row + 8) * (N >> 1) + wc] = pack2h(v2, v3);
                CL[(size_t)(row + 8) * (N >> 1) + wc] = packlo16(v2, v3);
            } else {
                *(float2*)&Cf[(size_t)row * N + col]       = make_float2(v0, v1);
                *(float2*)&Cf[(size_t)(row + 8) * N + col] = make_float2(v2, v3);
            }
        }
}

// ---------------------------------------------------------------------------
// Flash attention: Q split fp16 (hoisted), K/V single fp16 planes.
// Per buffer (words): K[64*36] @0, V @2304 -> 4608 (18 KB), 2 buffers.
// ---------------------------------------------------------------------------
#define AS 36
#define BUFW 4608
#define ATTN_SMEM (2 * BUFW * 4)     // 36864 B

__global__ void __launch_bounds__(128)
attn_kernel() {
    extern __shared__ uint32_t sw[];
    const uint32_t sb = smem_u32(sw);

    const int t = threadIdx.x;
    const int lane = t & 31;
    const int wid = t >> 5;
    const int h = blockIdx.y;
    const int qt = (int)gridDim.x - 1 - (int)blockIdx.x;
    const int qbase = qt * 64;
    const int hw0 = h * 32;

    // ---- stage Q into buf0 (K/V regions), extract frags ----
#pragma unroll
    for (int i = 0; i < 8; i++) {
        int idx = i * 128 + t;
        int row = idx >> 4;
        int w2  = (idx & 15) << 1;
        size_t src = (size_t)(qbase + row) * KW + hw0 + w2;
        *(uint2*)&sw[row * AS + w2]        = *(const uint2*)&g_QH[src];
        *(uint2*)&sw[2304 + row * AS + w2] = *(const uint2*)&g_QL[src];
    }
    __syncthreads();

    uint32_t qh[4][4], ql[4][4];
    {
        uint32_t qa = sb + ((wid * 16 + (lane & 15)) * AS + (lane >> 4) * 4) * 4;
#pragma unroll
        for (int kc = 0; kc < 4; kc++) {
            ldsm4(qh[kc], qa + kc * 32);
            ldsm4(ql[kc], qa + 2304 * 4 + kc * 32);
        }
    }
    __syncthreads();

    const int g = lane >> 3;
    const uint32_t bw = (((g >> 1) * 8 + (lane & 7)) * AS + (g & 1) * 4) * 4;

    auto issueKV = [&](int kt, int b) {
        uint32_t dstb = sb + (b * BUFW) * 4;
        size_t krow = (size_t)kt * 64;
        size_t tb = ((size_t)(h * 64 + kt)) << 11;
#pragma unroll
        for (int j = 0; j < 4; j++) {
            int idx = j * 128 + t;
            int row = idx >> 3;
            int seg = (idx & 7) << 2;
            uint32_t d0 = dstb + (row * AS + seg) * 4;
            CP_ASYNC16(d0,            &g_KP[(krow + row) * KW + hw0 + seg]);
            CP_ASYNC16(d0 + 2304 * 4, &g_VP[tb + row * 32 + seg]);
        }
    };

    float o[8][4];
#pragma unroll
    for (int nt = 0; nt < 8; nt++)
#pragma unroll
        for (int r = 0; r < 4; r++) o[nt][r] = 0.f;
    float m0 = -1e30f, m1 = -1e30f, l0 = 0.f, l1 = 0.f;

    issueKV(0, 0); CP_COMMIT();

    for (int kt = 0; kt <= qt; kt++) {
        if (kt < qt) { issueKV(kt + 1, (kt + 1) & 1); CP_COMMIT(); CP_WAIT1(); }
        else         { CP_WAIT0(); }
        __syncthreads();

        const uint32_t bufb = sb + ((kt & 1) * BUFW) * 4;

        // ---- S = Q K^T ----
        float s[8][4];
#pragma unroll
        for (int nt = 0; nt < 8; nt++)
#pragma unroll
            for (int r = 0; r < 4; r++) s[nt][r] = 0.f;

#pragma unroll
        for (int kc = 0; kc < 4; kc++) {
            uint32_t kh4[4][4];
#pragma unroll
            for (int p = 0; p < 4; p++)
                ldsm4(kh4[p], bufb + bw + (p * 16 * AS + kc * 8) * 4);
#pragma unroll
            for (int nt = 0; nt < 8; nt++) {
                const uint32_t* bp = &kh4[nt >> 1][(nt & 1) * 2];
                mma_fp16(s[nt], qh[kc], bp);
                mma_fp16(s[nt], ql[kc], bp);
            }
        }

        if (kt == qt) {
            int r0 = wid * 16 + (lane >> 2);
            int r1 = r0 + 8;
#pragma unroll
            for (int nt = 0; nt < 8; nt++) {
                int c0 = nt * 8 + 2 * (lane & 3);
                if (c0 > r0)     s[nt][0] = -1e30f;
                if (c0 + 1 > r0) s[nt][1] = -1e30f;
                if (c0 > r1)     s[nt][2] = -1e30f;
                if (c0 + 1 > r1) s[nt][3] = -1e30f;
            }
        }

        // ---- online softmax ----
        float rm0 = -1e30f, rm1 = -1e30f;
#pragma unroll
        for (int nt = 0; nt < 8; nt++) {
            rm0 = fmaxf(rm0, fmaxf(s[nt][0], s[nt][1]));
            rm1 = fmaxf(rm1, fmaxf(s[nt][2], s[nt][3]));
        }
        rm0 = fmaxf(rm0, __shfl_xor_sync(0xffffffffu, rm0, 1));
        rm0 = fmaxf(rm0, __shfl_xor_sync(0xffffffffu, rm0, 2));
        rm1 = fmaxf(rm1, __shfl_xor_sync(0xffffffffu, rm1, 1));
        rm1 = fmaxf(rm1, __shfl_xor_sync(0xffffffffu, rm1, 2));
        float mn0 = fmaxf(m0, rm0), mn1 = fmaxf(m1, rm1);
        float corr0 = __expf(m0 - mn0), corr1 = __expf(m1 - mn1);
        m0 = mn0; m1 = mn1;

        float sum0 = 0.f, sum1 = 0.f;
#pragma unroll
        for (int nt = 0; nt < 8; nt++) {
            s[nt][0] = __expf(s[nt][0] - mn0);
            s[nt][1] = __expf(s[nt][1] - mn0);
            s[nt][2] = __expf(s[nt][2] - mn1);
            s[nt][3] = __expf(s[nt][3] - mn1);
            sum0 += s[nt][0] + s[nt][1];
            sum1 += s[nt][2] + s[nt][3];
        }
        sum0 += __shfl_xor_sync(0xffffffffu, sum0, 1);
        sum0 += __shfl_xor_sync(0xffffffffu, sum0, 2);
        sum1 += __shfl_xor_sync(0xffffffffu, sum1, 1);
        sum1 += __shfl_xor_sync(0xffffffffu, sum1, 2);
        l0 = l0 * corr0 + sum0;
        l1 = l1 * corr1 + sum1;
#pragma unroll
        for (int nt = 0; nt < 8; nt++) {
            o[nt][0] *= corr0; o[nt][1] *= corr0;
            o[nt][2] *= corr1; o[nt][3] *= corr1;
        }

        // ---- O += P V  (P split fp16, V single) ----
#pragma unroll
        for (int kc = 0; kc < 4; kc++) {
            const float* sa = s[2 * kc];
            const float* sbv = s[2 * kc + 1];
            uint32_t ph[4], pl[4];
            ph[0] = pack2h(sa[0], sa[1]);
            ph[1] = pack2h(sa[2], sa[3]);
            ph[2] = pack2h(sbv[0], sbv[1]);
            ph[3] = pack2h(sbv[2], sbv[3]);
            pl[0] = packlo16(sa[0], sa[1]);
            pl[1] = packlo16(sa[2], sa[3]);
            pl[2] = packlo16(sbv[0], sbv[1]);
            pl[3] = packlo16(sbv[2], sbv[3]);

            uint32_t vh4[4][4];
#pragma unroll
            for (int p = 0; p < 4; p++)
                ldsm4(vh4[p], bufb + 2304 * 4 + bw + (p * 16 * AS + kc * 8) * 4);
#pragma unroll
            for (int nt = 0; nt < 8; nt++) {
                const uint32_t* vp = &vh4[nt >> 1][(nt & 1) * 2];
                mma_fp16(o[nt], ph, vp);
                mma_fp16(o[nt], pl, vp);
            }
        }
        __syncthreads();
    }

    // ---- write split output planes (fp16) ----
    float inv0 = 1.f / l0, inv1 = 1.f / l1;
    int row = qbase + wid * 16 + (lane >> 2);
#pragma unroll
    for (int nt = 0; nt < 8; nt++) {
        int wc = hw0 + nt * 4 + (lane & 3);
        float a0 = o[nt][0] * inv0, a1 = o[nt][1] * inv0;
        float b0 = o[nt][2] * inv1, b1 = o[nt][3] * inv1;
        g_AtH[(size_t)row * KW + wc]       = pack2h(a0, a1);
        g_AtL[(size_t)row * KW + wc]       = packlo16(a0, a1);
        g_AtH[(size_t)(row + 8) * KW + wc] = pack2h(b0, b1);
        g_AtL[(size_t)(row + 8) * KW + wc] = packlo16(b0, b1);
    }
}

// ---------------------------------------------------------------------------
// LayerNorm
// ---------------------------------------------------------------------------
__global__ void ln_kernel(const float* __restrict__ in,
                          const float* __restrict__ gamma,
                          float* __restrict__ out) {
    __shared__ float sbuf[8];
    const int row = blockIdx.x;
    const int t   = threadIdx.x;

    float4 v = *(const float4*)&in[(size_t)row * DIM + (t << 2)];

    float s = v.x + v.y + v.z + v.w;
#pragma unroll
    for (int o = 16; o; o >>= 1) s += __shfl_xor_sync(0xffffffffu, s, o);
    if ((t & 31) == 0) sbuf[t >> 5] = s;
    __syncthreads();
    float tot = sbuf[0] + sbuf[1] + sbuf[2] + sbuf[3] +
                sbuf[4] + sbuf[5] + sbuf[6] + sbuf[7];
    float mean = tot * (1.f / (float)DIM);
    __syncthreads();

    float dx = v.x - mean, dy = v.y - mean, dz = v.z - mean, dw = v.w - mean;
    float s2 = dx * dx + dy * dy + dz * dz + dw * dw;
#pragma unroll
    for (int o = 16; o; o >>= 1) s2 += __shfl_xor_sync(0xffffffffu, s2, o);
    if ((t & 31) == 0) sbuf[t >> 5] = s2;
    __syncthreads();
    float tot2 = sbuf[0] + sbuf[1] + sbuf[2] + sbuf[3] +
                 sbuf[4] + sbuf[5] + sbuf[6] + sbuf[7];
    float rstd = rsqrtf(tot2 * (1.f / (float)DIM) + 1e-5f);

    float4 gm = *(const float4*)&gamma[t << 2];
    float4 r;
    r.x = dx * rstd * gm.x;
    r.y = dy * rstd * gm.y;
    r.z = dz * rstd * gm.z;
    r.w = dw * rstd * gm.w;
    *(float4*)&out[(size_t)row * DIM + (t << 2)] = r;
}

// ---------------------------------------------------------------------------
// launch
// ---------------------------------------------------------------------------
extern "C" void kernel_launch(void* const* d_in, const int* in_sizes, int n_in,
                              void* d_out, int out_size) {
    const float* x     = (const float*)d_in[0];
    const float* Wqkv  = (const float*)d_in[1];
    const float* Wo1   = (const float*)d_in[2];
    const float* Wo2   = (const float*)d_in[3];
    const float* gamma = (const float*)d_in[4];
    float* out = (float*)d_out;

    float *qkv, *h2;
    uint32_t *XH, *XL, *AtH, *AtL, *H1H, *H1L;
    uint32_t *WqkvP, *Wo1P, *Wo2P;
    cudaGetSymbolAddress((void**)&qkv, g_qkv);
    cudaGetSymbolAddress((void**)&h2, g_h2);
    cudaGetSymbolAddress((void**)&XH, g_XH);
    cudaGetSymbolAddress((void**)&XL, g_XL);
    cudaGetSymbolAddress((void**)&AtH, g_AtH);
    cudaGetSymbolAddress((void**)&AtL, g_AtL);
    cudaGetSymbolAddress((void**)&H1H, g_H1H);
    cudaGetSymbolAddress((void**)&H1L, g_H1L);
    cudaGetSymbolAddress((void**)&WqkvP, g_WqkvP);
    cudaGetSymbolAddress((void**)&Wo1P, g_Wo1P);
    cudaGetSymbolAddress((void**)&Wo2P, g_Wo2P);

    static bool attr_done = false;
    if (!attr_done) {
        cudaFuncSetAttribute(attn_kernel,
                             cudaFuncAttributeMaxDynamicSharedMemorySize, ATTN_SMEM);
        cudaFuncSetAttribute(gemm_pre<0>,
                             cudaFuncAttributeMaxDynamicSharedMemorySize, GEMM_SMEM);
        cudaFuncSetAttribute(gemm_pre<1>,
                             cudaFuncAttributeMaxDynamicSharedMemorySize, GEMM_SMEM);
        attr_done = true;
    }

    split_x_kernel<<<(N_TOK * KW) / 256, 256>>>(x);
    split_w_kernel<<<dim3(QKV_N / 64, DIM / 64), 256>>>(Wqkv, WqkvP, DIM, QKV_N);
    split_w_kernel<<<dim3(DIM / 64, DIM / 64), 256>>>(Wo1, Wo1P, DIM, DIM);
    split_w_kernel<<<dim3(DIM / 64, DIM / 64), 256>>>(Wo2, Wo2P, DIM, DIM);

    gemm_pre<0><<<dim3(QKV_N / 128, N_TOK / 128), 512, GEMM_SMEM>>>(
        XH, XL, WqkvP, qkv, nullptr, nullptr, N_TOK, QKV_N, DIM);

    rope_split_kernel<<<(N_TOK * KW) / 256, 256>>>();
    v_prep_kernel<<<dim3(64, HEADS), 256>>>();

    attn_kernel<<<dim3(64, HEADS), 128, ATTN_SMEM>>>();

    gemm_pre<1><<<dim3(DIM / 128, N_TOK / 128), 512, GEMM_SMEM>>>(
        AtH, AtL, Wo1P, nullptr, H1H, H1L, N_TOK, DIM, DIM);

    gemm_pre<0><<<dim3(DIM / 128, N_TOK / 128), 512, GEMM_SMEM>>>(
        H1H, H1L, Wo2P, h2, nullptr, nullptr, N_TOK, DIM, DIM);

    ln_kernel<<<N_TOK, 256>>>(h2, gamma, out);
}

// round 7
// speedup vs baseline: 7.7195x; 1.1333x over previous
#include <cuda_runtime.h>
#include <cuda_bf16.h>
#include <cuda_fp16.h>
#include <math.h>
#include <stdint.h>

#define N_TOK   4096
#define DIM     1024
#define HEADS   16
#define HD      64
#define QKV_N   3072
#define KW      (DIM / 2)          // 512 packed words per 1024-dim row

// ---------------------------------------------------------------------------
// Scratch
// ---------------------------------------------------------------------------
__device__ float    g_qkv[N_TOK * QKV_N];
__device__ float    g_h2[N_TOK * DIM];
__device__ uint32_t g_XH[N_TOK * KW],  g_XL[N_TOK * KW];     // x split (fp16)
__device__ uint32_t g_QH[N_TOK * KW],  g_QL[N_TOK * KW];     // q split (fp16)
__device__ uint32_t g_KP[N_TOK * KW];                        // k single fp16
__device__ uint32_t g_VP[HEADS * 64 * 2048];                 // v single fp16 tiles
__device__ uint32_t g_AtH[N_TOK * KW], g_AtL[N_TOK * KW];
__device__ uint32_t g_H1H[N_TOK * KW], g_H1L[N_TOK * KW];
__device__ uint32_t g_WqkvP[QKV_N * KW];
__device__ uint32_t g_Wo1P[DIM * KW];
__device__ uint32_t g_Wo2P[DIM * KW];

// ---------------------------------------------------------------------------
// helpers
// ---------------------------------------------------------------------------
__device__ __forceinline__ float hff(float x) {
    return __half2float(__float2half_rn(x));
}
__device__ __forceinline__ uint32_t pack2h(float lo, float hi) {
    uint32_t r;
    asm("cvt.rn.f16x2.f32 %0, %1, %2;" : "=r"(r) : "f"(hi), "f"(lo));
    return r;
}
__device__ __forceinline__ uint32_t packlo16(float a, float b) {
    return pack2h(a - hff(a), b - hff(b));
}
__device__ __forceinline__ void mma_fp16(float* c, const uint32_t* a, const uint32_t* b) {
    asm volatile("mma.sync.aligned.m16n8k16.row.col.f32.f16.f16.f32 "
        "{%0,%1,%2,%3}, {%4,%5,%6,%7}, {%8,%9}, {%0,%1,%2,%3};"
        : "+f"(c[0]), "+f"(c[1]), "+f"(c[2]), "+f"(c[3])
        : "r"(a[0]), "r"(a[1]), "r"(a[2]), "r"(a[3]), "r"(b[0]), "r"(b[1]));
}
__device__ __forceinline__ void ldsm4(uint32_t* r, uint32_t addr) {
    asm volatile("ldmatrix.sync.aligned.m8n8.x4.shared.b16 {%0,%1,%2,%3}, [%4];"
        : "=r"(r[0]), "=r"(r[1]), "=r"(r[2]), "=r"(r[3]) : "r"(addr));
}
__device__ __forceinline__ uint32_t smem_u32(const void* p) {
    uint32_t a;
    asm("{ .reg .u64 t; cvta.to.shared.u64 t, %1; cvt.u32.u64 %0, t; }"
        : "=r"(a) : "l"(p));
    return a;
}
#define CP_ASYNC16(dst, src) \
    asm volatile("cp.async.cg.shared.global [%0], [%1], 16;" :: "r"(dst), "l"(src))
#define CP_COMMIT() asm volatile("cp.async.commit_group;")
#define CP_WAIT0()  asm volatile("cp.async.wait_group 0;")
#define CP_WAIT1()  asm volatile("cp.async.wait_group 1;")

// ---------------------------------------------------------------------------
// Prep kernels
// ---------------------------------------------------------------------------
__global__ void split_x_kernel(const float* __restrict__ x) {
    int idx = blockIdx.x * 256 + threadIdx.x;
    float2 v = *(const float2*)&x[(size_t)idx * 2];
    g_XH[idx] = pack2h(v.x, v.y);
    g_XL[idx] = packlo16(v.x, v.y);
}

__global__ void split_w_kernel(const float* __restrict__ W,
                               uint32_t* __restrict__ P, int K, int N) {
    __shared__ float S[64][68];
    const int t = threadIdx.x;
    const int k0 = blockIdx.y * 64, n0 = blockIdx.x * 64;
#pragma unroll
    for (int i = 0; i < 4; i++) {
        int slot = i * 256 + t;
        int k = slot >> 4, n4 = (slot & 15) << 2;
        *(float4*)&S[k][n4] = *(const float4*)&W[(size_t)(k0 + k) * N + n0 + n4];
    }
    __syncthreads();
    const int kw = K >> 1;
#pragma unroll
    for (int i = 0; i < 8; i++) {
        int slot = i * 256 + t;
        int n = slot >> 5, kwl = slot & 31;
        P[(size_t)(n0 + n) * kw + (k0 >> 1) + kwl] = pack2h(S[2 * kwl][n], S[2 * kwl + 1][n]);
    }
}

__global__ void rope_split_kernel() {
    int idx = blockIdx.x * 256 + threadIdx.x;
    int row  = idx >> 9;
    int hw   = idx & 511;
    int head = hw >> 5;
    int w    = hw & 31;
    int d0   = w * 2;
    int i0   = d0 & 31;

    float invf0 = powf(10000.f, -(float)i0 * (1.f / 32.f));
    float invf1 = powf(10000.f, -(float)(i0 + 1) * (1.f / 32.f));
    float s0, c0, s1, c1;
    sincosf((float)row * invf0, &s0, &c0);
    sincosf((float)row * invf1, &s1, &c1);

    bool half = (d0 < 32);
    size_t base = (size_t)row * QKV_N + head * HD + d0;
    size_t pb   = half ? base + 32 : base - 32;

    float q0 = g_qkv[base],       q1 = g_qkv[base + 1];
    float qp0 = g_qkv[pb],        qp1 = g_qkv[pb + 1];
    float k0 = g_qkv[base + DIM], k1 = g_qkv[base + DIM + 1];
    float kp0 = g_qkv[pb + DIM],  kp1 = g_qkv[pb + DIM + 1];

    float oq0, oq1, ok0, ok1;
    if (half) {
        oq0 = q0 * c0 - qp0 * s0;  oq1 = q1 * c1 - qp1 * s1;
        ok0 = k0 * c0 - kp0 * s0;  ok1 = k1 * c1 - kp1 * s1;
    } else {
        oq0 = q0 * c0 + qp0 * s0;  oq1 = q1 * c1 + qp1 * s1;
        ok0 = k0 * c0 + kp0 * s0;  ok1 = k1 * c1 + kp1 * s1;
    }
    oq0 *= 0.125f; oq1 *= 0.125f;

    g_QH[idx] = pack2h(oq0, oq1);
    g_QL[idx] = packlo16(oq0, oq1);
    g_KP[idx] = pack2h(ok0, ok1);
}

__global__ void v_prep_kernel() {
    __shared__ float S[64][68];
    const int t = threadIdx.x;
    const int kt = blockIdx.x, h = blockIdx.y;
#pragma unroll
    for (int i = 0; i < 4; i++) {
        int slot = i * 256 + t;
        int r = slot >> 4, c4 = (slot & 15) << 2;
        *(float4*)&S[r][c4] =
            *(const float4*)&g_qkv[(size_t)(kt * 64 + r) * QKV_N + 2 * DIM + h * HD + c4];
    }
    __syncthreads();
    size_t tb = ((size_t)(h * 64 + kt)) << 11;
#pragma unroll
    for (int i = 0; i < 8; i++) {
        int slot = i * 256 + t;
        int d = slot >> 5, p = slot & 31;
        g_VP[tb + slot] = pack2h(S[2 * p][d], S[2 * p + 1][d]);
    }
}

// ---------------------------------------------------------------------------
// GEMM: A split (AH,AL fp16) x B single (BP fp16), 2-term, 3-stage cp.async.
// Per buffer (words): Ah @0, Al @2560, B @5120 -> 7680 (30 KB), 3 buffers.
// ---------------------------------------------------------------------------
#define GS 20
#define GEMM_BUF_W (3 * 128 * GS)               // 7680 words
#define GEMM_SMEM  (3 * GEMM_BUF_W * 4)         // 92160 B

template <int MODE>
__global__ void __launch_bounds__(512)
gemm_pre(const uint32_t* __restrict__ AH, const uint32_t* __restrict__ AL,
         const uint32_t* __restrict__ BP,
         float* __restrict__ Cf, uint32_t* __restrict__ CH, uint32_t* __restrict__ CL,
         int M, int N, int K) {
    extern __shared__ uint32_t sw[];
    const int kw = K >> 1;
    const int t = threadIdx.x;
    const int lane = t & 31;
    const int wid = t >> 5;
    const int wm = wid & 3;
    const int wn = wid >> 2;
    const int bm = blockIdx.y * 128;
    const int bn = blockIdx.x * 128;
    const uint32_t sb = smem_u32(sw);

    const int frow = t >> 2;
    const int fw4  = (t & 3) << 2;
    const uint32_t* sAH = &AH[(size_t)(bm + frow) * kw + fw4];
    const uint32_t* sAL = &AL[(size_t)(bm + frow) * kw + fw4];
    const uint32_t* sBP = &BP[(size_t)(bn + frow) * kw + fw4];
    const uint32_t dbase = sb + (frow * GS + fw4) * 4;

    auto issue = [&](int c, int b) {
        uint32_t d = dbase + (b * GEMM_BUF_W) * 4;
        int go = c * 16;
        CP_ASYNC16(d,            sAH + go);
        CP_ASYNC16(d + 2560 * 4, sAL + go);
        CP_ASYNC16(d + 5120 * 4, sBP + go);
    };

    const uint32_t aw = ((wm * 32 + (lane & 15)) * GS + (lane >> 4) * 4) * 4;
    const int g = lane >> 3;
    const uint32_t bw = ((wn * 32 + (g >> 1) * 8 + (lane & 7)) * GS + (g & 1) * 4) * 4;

    float acc[2][4][4];
#pragma unroll
    for (int i = 0; i < 2; i++)
#pragma unroll
        for (int j = 0; j < 4; j++)
#pragma unroll
            for (int r = 0; r < 4; r++) acc[i][j][r] = 0.f;

    const int nch = K / 32;
    issue(0, 0); CP_COMMIT();
    if (nch > 1) { issue(1, 1); CP_COMMIT(); }

    for (int c = 0; c < nch; c++) {
        if (c + 1 < nch) CP_WAIT1(); else CP_WAIT0();
        __syncthreads();
        if (c + 2 < nch) { issue(c + 2, (c + 2) % 3); CP_COMMIT(); }

        const uint32_t bufb = sb + ((c % 3) * GEMM_BUF_W) * 4;

#pragma unroll
        for (int ks = 0; ks < 2; ks++) {
            uint32_t ah[2][4], al[2][4], bp[2][4];
#pragma unroll
            for (int mt = 0; mt < 2; mt++) {
                uint32_t ad = bufb + aw + (mt * 16 * GS + ks * 8) * 4;
                ldsm4(ah[mt], ad);
                ldsm4(al[mt], ad + 2560 * 4);
            }
#pragma unroll
            for (int p = 0; p < 2; p++) {
                uint32_t bd = bufb + bw + (p * 16 * GS + ks * 8) * 4;
                ldsm4(bp[p], bd + 5120 * 4);
            }
#pragma unroll
            for (int mt = 0; mt < 2; mt++)
#pragma unroll
                for (int nt = 0; nt < 4; nt++) {
                    const uint32_t* bpp = &bp[nt >> 1][(nt & 1) * 2];
                    mma_fp16(acc[mt][nt], ah[mt], bpp);
                    mma_fp16(acc[mt][nt], al[mt], bpp);
                }
        }
    }

#pragma unroll
    for (int mt = 0; mt < 2; mt++)
#pragma unroll
        for (int nt = 0; nt < 4; nt++) {
            int row = bm + wm * 32 + mt * 16 + (lane >> 2);
            int col = bn + wn * 32 + nt * 8 + 2 * (lane & 3);
            float v0 = acc[mt][nt][0], v1 = acc[mt][nt][1];
            float v2 = acc[mt][nt][2], v3 = acc[mt][nt][3];
            if (MODE == 1) {
                v0 = fmaxf(v0, 0.f); v1 = fmaxf(v1, 0.f);
                v2 = fmaxf(v2, 0.f); v3 = fmaxf(v3, 0.f);
                int wc = col >> 1;
                CH[(size_t)row * (N >> 1) + wc]       = pack2h(v0, v1);
                CL[(size_t)row * (N >> 1) + wc]       = packlo16(v0, v1);
                CH[(size_t)(row + 8) * (N >> 1) + wc] = pack2h(v2, v3);
                CL[(size_t)(row + 8) * (N >> 1) + wc] = packlo16(v2, v3);
            } else {
                *(float2*)&Cf[(size_t)row * N + col]       = make_float2(v0, v1);
                *(float2*)&Cf[(size_t)(row + 8) * N + col] = make_float2(v2, v3);
            }
        }
}

// ---------------------------------------------------------------------------
// Flash attention: Q split fp16 (hoisted), K/V single fp16, 3-stage cp.async,
// one barrier per kv tile, P-hi-only PV.
// Per buffer (words): K[64*36] @0, V @2304 -> 4608 (18 KB), 3 buffers.
// ---------------------------------------------------------------------------
#define AS 36
#define BUFW 4608
#define ATTN_SMEM (3 * BUFW * 4)     // 55296 B

__global__ void __launch_bounds__(128)
attn_kernel() {
    extern __shared__ uint32_t sw[];
    const uint32_t sb = smem_u32(sw);

    const int t = threadIdx.x;
    const int lane = t & 31;
    const int wid = t >> 5;
    const int h = blockIdx.y;
    const int qt = (int)gridDim.x - 1 - (int)blockIdx.x;
    const int qbase = qt * 64;
    const int hw0 = h * 32;

    // ---- stage Q into buffers 0-1 region, extract frags ----
#pragma unroll
    for (int i = 0; i < 8; i++) {
        int idx = i * 128 + t;
        int row = idx >> 4;
        int w2  = (idx & 15) << 1;
        size_t src = (size_t)(qbase + row) * KW + hw0 + w2;
        *(uint2*)&sw[row * AS + w2]        = *(const uint2*)&g_QH[src];
        *(uint2*)&sw[2304 + row * AS + w2] = *(const uint2*)&g_QL[src];
    }
    __syncthreads();

    uint32_t qh[4][4], ql[4][4];
    {
        uint32_t qa = sb + ((wid * 16 + (lane & 15)) * AS + (lane >> 4) * 4) * 4;
#pragma unroll
        for (int kc = 0; kc < 4; kc++) {
            ldsm4(qh[kc], qa + kc * 32);
            ldsm4(ql[kc], qa + 2304 * 4 + kc * 32);
        }
    }
    __syncthreads();

    const int g = lane >> 3;
    const uint32_t bw = (((g >> 1) * 8 + (lane & 7)) * AS + (g & 1) * 4) * 4;

    auto issueKV = [&](int kt, int b) {
        uint32_t dstb = sb + (b * BUFW) * 4;
        size_t krow = (size_t)kt * 64;
        size_t tb = ((size_t)(h * 64 + kt)) << 11;
#pragma unroll
        for (int j = 0; j < 4; j++) {
            int idx = j * 128 + t;
            int row = idx >> 3;
            int seg = (idx & 7) << 2;
            uint32_t d0 = dstb + (row * AS + seg) * 4;
            CP_ASYNC16(d0,            &g_KP[(krow + row) * KW + hw0 + seg]);
            CP_ASYNC16(d0 + 2304 * 4, &g_VP[tb + row * 32 + seg]);
        }
    };

    float o[8][4];
#pragma unroll
    for (int nt = 0; nt < 8; nt++)
#pragma unroll
        for (int r = 0; r < 4; r++) o[nt][r] = 0.f;
    float m0 = -1e30f, m1 = -1e30f, l0 = 0.f, l1 = 0.f;

    issueKV(0, 0); CP_COMMIT();
    if (qt >= 1) { issueKV(1, 1); CP_COMMIT(); }

    for (int kt = 0; kt <= qt; kt++) {
        if (kt < qt) CP_WAIT1(); else CP_WAIT0();
        __syncthreads();
        if (kt + 2 <= qt) { issueKV(kt + 2, (kt + 2) % 3); CP_COMMIT(); }

        const uint32_t bufb = sb + ((kt % 3) * BUFW) * 4;

        // ---- S = Q K^T ----
        float s[8][4];
#pragma unroll
        for (int nt = 0; nt < 8; nt++)
#pragma unroll
            for (int r = 0; r < 4; r++) s[nt][r] = 0.f;

#pragma unroll
        for (int kc = 0; kc < 4; kc++) {
            uint32_t kh4[4][4];
#pragma unroll
            for (int p = 0; p < 4; p++)
                ldsm4(kh4[p], bufb + bw + (p * 16 * AS + kc * 8) * 4);
#pragma unroll
            for (int nt = 0; nt < 8; nt++) {
                const uint32_t* bp = &kh4[nt >> 1][(nt & 1) * 2];
                mma_fp16(s[nt], qh[kc], bp);
                mma_fp16(s[nt], ql[kc], bp);
            }
        }

        if (kt == qt) {
            int r0 = wid * 16 + (lane >> 2);
            int r1 = r0 + 8;
#pragma unroll
            for (int nt = 0; nt < 8; nt++) {
                int c0 = nt * 8 + 2 * (lane & 3);
                if (c0 > r0)     s[nt][0] = -1e30f;
                if (c0 + 1 > r0) s[nt][1] = -1e30f;
                if (c0 > r1)     s[nt][2] = -1e30f;
                if (c0 + 1 > r1) s[nt][3] = -1e30f;
            }
        }

        // ---- online softmax ----
        float rm0 = -1e30f, rm1 = -1e30f;
#pragma unroll
        for (int nt = 0; nt < 8; nt++) {
            rm0 = fmaxf(rm0, fmaxf(s[nt][0], s[nt][1]));
            rm1 = fmaxf(rm1, fmaxf(s[nt][2], s[nt][3]));
        }
        rm0 = fmaxf(rm0, __shfl_xor_sync(0xffffffffu, rm0, 1));
        rm0 = fmaxf(rm0, __shfl_xor_sync(0xffffffffu, rm0, 2));
        rm1 = fmaxf(rm1, __shfl_xor_sync(0xffffffffu, rm1, 1));
        rm1 = fmaxf(rm1, __shfl_xor_sync(0xffffffffu, rm1, 2));
        float mn0 = fmaxf(m0, rm0), mn1 = fmaxf(m1, rm1);
        float corr0 = __expf(m0 - mn0), corr1 = __expf(m1 - mn1);
        m0 = mn0; m1 = mn1;

        float sum0 = 0.f, sum1 = 0.f;
#pragma unroll
        for (int nt = 0; nt < 8; nt++) {
            s[nt][0] = __expf(s[nt][0] - mn0);
            s[nt][1] = __expf(s[nt][1] - mn0);
            s[nt][2] = __expf(s[nt][2] - mn1);
            s[nt][3] = __expf(s[nt][3] - mn1);
            sum0 += s[nt][0] + s[nt][1];
            sum1 += s[nt][2] + s[nt][3];
        }
        sum0 += __shfl_xor_sync(0xffffffffu, sum0, 1);
        sum0 += __shfl_xor_sync(0xffffffffu, sum0, 2);
        sum1 += __shfl_xor_sync(0xffffffffu, sum1, 1);
        sum1 += __shfl_xor_sync(0xffffffffu, sum1, 2);
        l0 = l0 * corr0 + sum0;
        l1 = l1 * corr1 + sum1;
#pragma unroll
        for (int nt = 0; nt < 8; nt++) {
            o[nt][0] *= corr0; o[nt][1] *= corr0;
            o[nt][2] *= corr1; o[nt][3] *= corr1;
        }

        // ---- O += P V  (P hi only) ----
#pragma unroll
        for (int kc = 0; kc < 4; kc++) {
            const float* sa = s[2 * kc];
            const float* sbv = s[2 * kc + 1];
            uint32_t ph[4];
            ph[0] = pack2h(sa[0], sa[1]);
            ph[1] = pack2h(sa[2], sa[3]);
            ph[2] = pack2h(sbv[0], sbv[1]);
            ph[3] = pack2h(sbv[2], sbv[3]);

            uint32_t vh4[4][4];
#pragma unroll
            for (int p = 0; p < 4; p++)
                ldsm4(vh4[p], bufb + 2304 * 4 + bw + (p * 16 * AS + kc * 8) * 4);
#pragma unroll
            for (int nt = 0; nt < 8; nt++)
                mma_fp16(o[nt], ph, &vh4[nt >> 1][(nt & 1) * 2]);
        }
    }

    // ---- write split output planes (fp16) ----
    float inv0 = 1.f / l0, inv1 = 1.f / l1;
    int row = qbase + wid * 16 + (lane >> 2);
#pragma unroll
    for (int nt = 0; nt < 8; nt++) {
        int wc = hw0 + nt * 4 + (lane & 3);
        float a0 = o[nt][0] * inv0, a1 = o[nt][1] * inv0;
        float b0 = o[nt][2] * inv1, b1 = o[nt][3] * inv1;
        g_AtH[(size_t)row * KW + wc]       = pack2h(a0, a1);
        g_AtL[(size_t)row * KW + wc]       = packlo16(a0, a1);
        g_AtH[(size_t)(row + 8) * KW + wc] = pack2h(b0, b1);
        g_AtL[(size_t)(row + 8) * KW + wc] = packlo16(b0, b1);
    }
}

// ---------------------------------------------------------------------------
// LayerNorm
// ---------------------------------------------------------------------------
__global__ void ln_kernel(const float* __restrict__ in,
                          const float* __restrict__ gamma,
                          float* __restrict__ out) {
    __shared__ float sbuf[8];
    const int row = blockIdx.x;
    const int t   = threadIdx.x;

    float4 v = *(const float4*)&in[(size_t)row * DIM + (t << 2)];

    float s = v.x + v.y + v.z + v.w;
#pragma unroll
    for (int o = 16; o; o >>= 1) s += __shfl_xor_sync(0xffffffffu, s, o);
    if ((t & 31) == 0) sbuf[t >> 5] = s;
    __syncthreads();
    float tot = sbuf[0] + sbuf[1] + sbuf[2] + sbuf[3] +
                sbuf[4] + sbuf[5] + sbuf[6] + sbuf[7];
    float mean = tot * (1.f / (float)DIM);
    __syncthreads();

    float dx = v.x - mean, dy = v.y - mean, dz = v.z - mean, dw = v.w - mean;
    float s2 = dx * dx + dy * dy + dz * dz + dw * dw;
#pragma unroll
    for (int o = 16; o; o >>= 1) s2 += __shfl_xor_sync(0xffffffffu, s2, o);
    if ((t & 31) == 0) sbuf[t >> 5] = s2;
    __syncthreads();
    float tot2 = sbuf[0] + sbuf[1] + sbuf[2] + sbuf[3] +
                 sbuf[4] + sbuf[5] + sbuf[6] + sbuf[7];
    float rstd = rsqrtf(tot2 * (1.f / (float)DIM) + 1e-5f);

    float4 gm = *(const float4*)&gamma[t << 2];
    float4 r;
    r.x = dx * rstd * gm.x;
    r.y = dy * rstd * gm.y;
    r.z = dz * rstd * gm.z;
    r.w = dw * rstd * gm.w;
    *(float4*)&out[(size_t)row * DIM + (t << 2)] = r;
}

// ---------------------------------------------------------------------------
// launch
// ---------------------------------------------------------------------------
extern "C" void kernel_launch(void* const* d_in, const int* in_sizes, int n_in,
                              void* d_out, int out_size) {
    const float* x     = (const float*)d_in[0];
    const float* Wqkv  = (const float*)d_in[1];
    const float* Wo1   = (const float*)d_in[2];
    const float* Wo2   = (const float*)d_in[3];
    const float* gamma = (const float*)d_in[4];
    float* out = (float*)d_out;

    float *qkv, *h2;
    uint32_t *XH, *XL, *AtH, *AtL, *H1H, *H1L;
    uint32_t *WqkvP, *Wo1P, *Wo2P;
    cudaGetSymbolAddress((void**)&qkv, g_qkv);
    cudaGetSymbolAddress((void**)&h2, g_h2);
    cudaGetSymbolAddress((void**)&XH, g_XH);
    cudaGetSymbolAddress((void**)&XL, g_XL);
    cudaGetSymbolAddress((void**)&AtH, g_AtH);
    cudaGetSymbolAddress((void**)&AtL, g_AtL);
    cudaGetSymbolAddress((void**)&H1H, g_H1H);
    cudaGetSymbolAddress((void**)&H1L, g_H1L);
    cudaGetSymbolAddress((void**)&WqkvP, g_WqkvP);
    cudaGetSymbolAddress((void**)&Wo1P, g_Wo1P);
    cudaGetSymbolAddress((void**)&Wo2P, g_Wo2P);

    static bool attr_done = false;
    if (!attr_done) {
        cudaFuncSetAttribute(attn_kernel,
                             cudaFuncAttributeMaxDynamicSharedMemorySize, ATTN_SMEM);
        cudaFuncSetAttribute(gemm_pre<0>,
                             cudaFuncAttributeMaxDynamicSharedMemorySize, GEMM_SMEM);
        cudaFuncSetAttribute(gemm_pre<1>,
                             cudaFuncAttributeMaxDynamicSharedMemorySize, GEMM_SMEM);
        attr_done = true;
    }

    split_x_kernel<<<(N_TOK * KW) / 256, 256>>>(x);
    split_w_kernel<<<dim3(QKV_N / 64, DIM / 64), 256>>>(Wqkv, WqkvP, DIM, QKV_N);
    split_w_kernel<<<dim3(DIM / 64, DIM / 64), 256>>>(Wo1, Wo1P, DIM, DIM);
    split_w_kernel<<<dim3(DIM / 64, DIM / 64), 256>>>(Wo2, Wo2P, DIM, DIM);

    gemm_pre<0><<<dim3(QKV_N / 128, N_TOK / 128), 512, GEMM_SMEM>>>(
        XH, XL, WqkvP, qkv, nullptr, nullptr, N_TOK, QKV_N, DIM);

    rope_split_kernel<<<(N_TOK * KW) / 256, 256>>>();
    v_prep_kernel<<<dim3(64, HEADS), 256>>>();

    attn_kernel<<<dim3(64, HEADS), 128, ATTN_SMEM>>>();

    gemm_pre<1><<<dim3(DIM / 128, N_TOK / 128), 512, GEMM_SMEM>>>(
        AtH, AtL, Wo1P, nullptr, H1H, H1L, N_TOK, DIM, DIM);

    gemm_pre<0><<<dim3(DIM / 128, N_TOK / 128), 512, GEMM_SMEM>>>(
        H1H, H1L, Wo2P, h2, nullptr, nullptr, N_TOK, DIM, DIM);

    ln_kernel<<<N_TOK, 256>>>(h2, gamma, out);
}

// round 8
// speedup vs baseline: 11.7803x; 1.5260x over previous
#include <cuda_runtime.h>
#include <cuda_bf16.h>
#include <cuda_fp16.h>
#include <math.h>
#include <stdint.h>

#define N_TOK   4096
#define DIM     1024
#define HEADS   16
#define HD      64
#define QKV_N   3072
#define KW      (DIM / 2)          // 512 packed fp16x2 words per 1024-dim row

// ---------------------------------------------------------------------------
// Scratch (all operand planes single fp16, packed 2/word)
// ---------------------------------------------------------------------------
__device__ float    g_qkv[N_TOK * QKV_N];
__device__ float    g_h2[N_TOK * DIM];
__device__ uint32_t g_XP[N_TOK * KW];                        // x fp16
__device__ uint32_t g_QP[N_TOK * KW];                        // q fp16 (roped, scaled)
__device__ uint32_t g_KP[N_TOK * KW];                        // k fp16 (roped)
__device__ uint32_t g_VP[HEADS * 64 * 2048];                 // v fp16 transposed tiles
__device__ uint32_t g_AtP[N_TOK * KW];                       // attention out fp16
__device__ uint32_t g_H1P[N_TOK * KW];                       // relu(h1) fp16
__device__ uint32_t g_WqkvP[QKV_N * KW];
__device__ uint32_t g_Wo1P[DIM * KW];
__device__ uint32_t g_Wo2P[DIM * KW];

// ---------------------------------------------------------------------------
// helpers
// ---------------------------------------------------------------------------
__device__ __forceinline__ uint32_t pack2h(float lo, float hi) {
    uint32_t r;
    asm("cvt.rn.f16x2.f32 %0, %1, %2;" : "=r"(r) : "f"(hi), "f"(lo));
    return r;
}
__device__ __forceinline__ void mma_fp16(float* c, const uint32_t* a, const uint32_t* b) {
    asm volatile("mma.sync.aligned.m16n8k16.row.col.f32.f16.f16.f32 "
        "{%0,%1,%2,%3}, {%4,%5,%6,%7}, {%8,%9}, {%0,%1,%2,%3};"
        : "+f"(c[0]), "+f"(c[1]), "+f"(c[2]), "+f"(c[3])
        : "r"(a[0]), "r"(a[1]), "r"(a[2]), "r"(a[3]), "r"(b[0]), "r"(b[1]));
}
__device__ __forceinline__ void ldsm4(uint32_t* r, uint32_t addr) {
    asm volatile("ldmatrix.sync.aligned.m8n8.x4.shared.b16 {%0,%1,%2,%3}, [%4];"
        : "=r"(r[0]), "=r"(r[1]), "=r"(r[2]), "=r"(r[3]) : "r"(addr));
}
__device__ __forceinline__ uint32_t smem_u32(const void* p) {
    uint32_t a;
    asm("{ .reg .u64 t; cvta.to.shared.u64 t, %1; cvt.u32.u64 %0, t; }"
        : "=r"(a) : "l"(p));
    return a;
}
#define CP_ASYNC16(dst, src) \
    asm volatile("cp.async.cg.shared.global [%0], [%1], 16;" :: "r"(dst), "l"(src))
#define CP_COMMIT() asm volatile("cp.async.commit_group;")
#define CP_WAIT0()  asm volatile("cp.async.wait_group 0;")
#define CP_WAIT1()  asm volatile("cp.async.wait_group 1;")

// ---------------------------------------------------------------------------
// Prep kernels
// ---------------------------------------------------------------------------
__global__ void split_x_kernel(const float* __restrict__ x) {
    int idx = blockIdx.x * 256 + threadIdx.x;
    float2 v = *(const float2*)&x[(size_t)idx * 2];
    g_XP[idx] = pack2h(v.x, v.y);
}

__global__ void split_w_kernel(const float* __restrict__ W,
                               uint32_t* __restrict__ P, int K, int N) {
    __shared__ float S[64][68];
    const int t = threadIdx.x;
    const int k0 = blockIdx.y * 64, n0 = blockIdx.x * 64;
#pragma unroll
    for (int i = 0; i < 4; i++) {
        int slot = i * 256 + t;
        int k = slot >> 4, n4 = (slot & 15) << 2;
        *(float4*)&S[k][n4] = *(const float4*)&W[(size_t)(k0 + k) * N + n0 + n4];
    }
    __syncthreads();
    const int kw = K >> 1;
#pragma unroll
    for (int i = 0; i < 8; i++) {
        int slot = i * 256 + t;
        int n = slot >> 5, kwl = slot & 31;
        P[(size_t)(n0 + n) * kw + (k0 >> 1) + kwl] = pack2h(S[2 * kwl][n], S[2 * kwl + 1][n]);
    }
}

__global__ void rope_split_kernel() {
    int idx = blockIdx.x * 256 + threadIdx.x;
    int row  = idx >> 9;
    int hw   = idx & 511;
    int head = hw >> 5;
    int w    = hw & 31;
    int d0   = w * 2;
    int i0   = d0 & 31;

    float invf0 = powf(10000.f, -(float)i0 * (1.f / 32.f));
    float invf1 = powf(10000.f, -(float)(i0 + 1) * (1.f / 32.f));
    float s0, c0, s1, c1;
    sincosf((float)row * invf0, &s0, &c0);
    sincosf((float)row * invf1, &s1, &c1);

    bool half = (d0 < 32);
    size_t base = (size_t)row * QKV_N + head * HD + d0;
    size_t pb   = half ? base + 32 : base - 32;

    float q0 = g_qkv[base],       q1 = g_qkv[base + 1];
    float qp0 = g_qkv[pb],        qp1 = g_qkv[pb + 1];
    float k0 = g_qkv[base + DIM], k1 = g_qkv[base + DIM + 1];
    float kp0 = g_qkv[pb + DIM],  kp1 = g_qkv[pb + DIM + 1];

    float oq0, oq1, ok0, ok1;
    if (half) {
        oq0 = q0 * c0 - qp0 * s0;  oq1 = q1 * c1 - qp1 * s1;
        ok0 = k0 * c0 - kp0 * s0;  ok1 = k1 * c1 - kp1 * s1;
    } else {
        oq0 = q0 * c0 + qp0 * s0;  oq1 = q1 * c1 + qp1 * s1;
        ok0 = k0 * c0 + kp0 * s0;  ok1 = k1 * c1 + kp1 * s1;
    }
    oq0 *= 0.125f; oq1 *= 0.125f;

    g_QP[idx] = pack2h(oq0, oq1);
    g_KP[idx] = pack2h(ok0, ok1);
}

__global__ void v_prep_kernel() {
    __shared__ float S[64][68];
    const int t = threadIdx.x;
    const int kt = blockIdx.x, h = blockIdx.y;
#pragma unroll
    for (int i = 0; i < 4; i++) {
        int slot = i * 256 + t;
        int r = slot >> 4, c4 = (slot & 15) << 2;
        *(float4*)&S[r][c4] =
            *(const float4*)&g_qkv[(size_t)(kt * 64 + r) * QKV_N + 2 * DIM + h * HD + c4];
    }
    __syncthreads();
    size_t tb = ((size_t)(h * 64 + kt)) << 11;
#pragma unroll
    for (int i = 0; i < 8; i++) {
        int slot = i * 256 + t;
        int d = slot >> 5, p = slot & 31;
        g_VP[tb + slot] = pack2h(S[2 * p][d], S[2 * p + 1][d]);
    }
}

// ---------------------------------------------------------------------------
// GEMM: single fp16 A x single fp16 B, 3-stage cp.async, ldmatrix feeds.
// Per buffer (words): A @0 (2560), B @2560 -> 5120 (20 KB), 3 buffers.
// ---------------------------------------------------------------------------
#define GS 20
#define GEMM_BUF_W (2 * 128 * GS)               // 5120 words
#define GEMM_SMEM  (3 * GEMM_BUF_W * 4)         // 61440 B

template <int MODE>
__global__ void __launch_bounds__(512)
gemm_pre(const uint32_t* __restrict__ AP, const uint32_t* __restrict__ BP,
         float* __restrict__ Cf, uint32_t* __restrict__ CP,
         int M, int N, int K) {
    extern __shared__ uint32_t sw[];
    const int kw = K >> 1;
    const int t = threadIdx.x;
    const int lane = t & 31;
    const int wid = t >> 5;
    const int wm = wid & 3;
    const int wn = wid >> 2;
    const int bm = blockIdx.y * 128;
    const int bn = blockIdx.x * 128;
    const uint32_t sb = smem_u32(sw);

    const int frow = t >> 2;
    const int fw4  = (t & 3) << 2;
    const uint32_t* sAP = &AP[(size_t)(bm + frow) * kw + fw4];
    const uint32_t* sBP = &BP[(size_t)(bn + frow) * kw + fw4];
    const uint32_t dbase = sb + (frow * GS + fw4) * 4;

    auto issue = [&](int c, int b) {
        uint32_t d = dbase + (b * GEMM_BUF_W) * 4;
        int go = c * 16;
        CP_ASYNC16(d,            sAP + go);
        CP_ASYNC16(d + 2560 * 4, sBP + go);
    };

    const uint32_t aw = ((wm * 32 + (lane & 15)) * GS + (lane >> 4) * 4) * 4;
    const int g = lane >> 3;
    const uint32_t bw = ((wn * 32 + (g >> 1) * 8 + (lane & 7)) * GS + (g & 1) * 4) * 4;

    float acc[2][4][4];
#pragma unroll
    for (int i = 0; i < 2; i++)
#pragma unroll
        for (int j = 0; j < 4; j++)
#pragma unroll
            for (int r = 0; r < 4; r++) acc[i][j][r] = 0.f;

    const int nch = K / 32;
    issue(0, 0); CP_COMMIT();
    if (nch > 1) { issue(1, 1); CP_COMMIT(); }

    for (int c = 0; c < nch; c++) {
        if (c + 1 < nch) CP_WAIT1(); else CP_WAIT0();
        __syncthreads();
        if (c + 2 < nch) { issue(c + 2, (c + 2) % 3); CP_COMMIT(); }

        const uint32_t bufb = sb + ((c % 3) * GEMM_BUF_W) * 4;

#pragma unroll
        for (int ks = 0; ks < 2; ks++) {
            uint32_t ah[2][4], bp[2][4];
#pragma unroll
            for (int mt = 0; mt < 2; mt++)
                ldsm4(ah[mt], bufb + aw + (mt * 16 * GS + ks * 8) * 4);
#pragma unroll
            for (int p = 0; p < 2; p++)
                ldsm4(bp[p], bufb + 2560 * 4 + bw + (p * 16 * GS + ks * 8) * 4);
#pragma unroll
            for (int mt = 0; mt < 2; mt++)
#pragma unroll
                for (int nt = 0; nt < 4; nt++)
                    mma_fp16(acc[mt][nt], ah[mt], &bp[nt >> 1][(nt & 1) * 2]);
        }
    }

#pragma unroll
    for (int mt = 0; mt < 2; mt++)
#pragma unroll
        for (int nt = 0; nt < 4; nt++) {
            int row = bm + wm * 32 + mt * 16 + (lane >> 2);
            int col = bn + wn * 32 + nt * 8 + 2 * (lane & 3);
            float v0 = acc[mt][nt][0], v1 = acc[mt][nt][1];
            float v2 = acc[mt][nt][2], v3 = acc[mt][nt][3];
            if (MODE == 1) {
                v0 = fmaxf(v0, 0.f); v1 = fmaxf(v1, 0.f);
                v2 = fmaxf(v2, 0.f); v3 = fmaxf(v3, 0.f);
                int wc = col >> 1;
                CP[(size_t)row * (N >> 1) + wc]       = pack2h(v0, v1);
                CP[(size_t)(row + 8) * (N >> 1) + wc] = pack2h(v2, v3);
            } else {
                *(float2*)&Cf[(size_t)row * N + col]       = make_float2(v0, v1);
                *(float2*)&Cf[(size_t)(row + 8) * N + col] = make_float2(v2, v3);
            }
        }
}

// ---------------------------------------------------------------------------
// Flash attention: single fp16 Q (hoisted), K/V single fp16, 3-stage cp.async.
// Per buffer (words): K[64*36] @0, V @2304 -> 4608 (18 KB), 3 buffers.
// ---------------------------------------------------------------------------
#define AS 36
#define BUFW 4608
#define ATTN_SMEM (3 * BUFW * 4)     // 55296 B

__global__ void __launch_bounds__(128)
attn_kernel() {
    extern __shared__ uint32_t sw[];
    const uint32_t sb = smem_u32(sw);

    const int t = threadIdx.x;
    const int lane = t & 31;
    const int wid = t >> 5;
    const int h = blockIdx.y;
    const int qt = (int)gridDim.x - 1 - (int)blockIdx.x;
    const int qbase = qt * 64;
    const int hw0 = h * 32;

    // ---- stage Q, extract frags ----
#pragma unroll
    for (int i = 0; i < 8; i++) {
        int idx = i * 128 + t;
        int row = idx >> 4;
        int w2  = (idx & 15) << 1;
        *(uint2*)&sw[row * AS + w2] =
            *(const uint2*)&g_QP[(size_t)(qbase + row) * KW + hw0 + w2];
    }
    __syncthreads();

    uint32_t qh[4][4];
    {
        uint32_t qa = sb + ((wid * 16 + (lane & 15)) * AS + (lane >> 4) * 4) * 4;
#pragma unroll
        for (int kc = 0; kc < 4; kc++)
            ldsm4(qh[kc], qa + kc * 32);
    }
    __syncthreads();

    const int g = lane >> 3;
    const uint32_t bw = (((g >> 1) * 8 + (lane & 7)) * AS + (g & 1) * 4) * 4;

    auto issueKV = [&](int kt, int b) {
        uint32_t dstb = sb + (b * BUFW) * 4;
        size_t krow = (size_t)kt * 64;
        size_t tb = ((size_t)(h * 64 + kt)) << 11;
#pragma unroll
        for (int j = 0; j < 4; j++) {
            int idx = j * 128 + t;
            int row = idx >> 3;
            int seg = (idx & 7) << 2;
            uint32_t d0 = dstb + (row * AS + seg) * 4;
            CP_ASYNC16(d0,            &g_KP[(krow + row) * KW + hw0 + seg]);
            CP_ASYNC16(d0 + 2304 * 4, &g_VP[tb + row * 32 + seg]);
        }
    };

    float o[8][4];
#pragma unroll
    for (int nt = 0; nt < 8; nt++)
#pragma unroll
        for (int r = 0; r < 4; r++) o[nt][r] = 0.f;
    float m0 = -1e30f, m1 = -1e30f, l0 = 0.f, l1 = 0.f;

    issueKV(0, 0); CP_COMMIT();
    if (qt >= 1) { issueKV(1, 1); CP_COMMIT(); }

    for (int kt = 0; kt <= qt; kt++) {
        if (kt < qt) CP_WAIT1(); else CP_WAIT0();
        __syncthreads();
        if (kt + 2 <= qt) { issueKV(kt + 2, (kt + 2) % 3); CP_COMMIT(); }

        const uint32_t bufb = sb + ((kt % 3) * BUFW) * 4;

        // ---- S = Q K^T ----
        float s[8][4];
#pragma unroll
        for (int nt = 0; nt < 8; nt++)
#pragma unroll
            for (int r = 0; r < 4; r++) s[nt][r] = 0.f;

#pragma unroll
        for (int kc = 0; kc < 4; kc++) {
            uint32_t kh4[4][4];
#pragma unroll
            for (int p = 0; p < 4; p++)
                ldsm4(kh4[p], bufb + bw + (p * 16 * AS + kc * 8) * 4);
#pragma unroll
            for (int nt = 0; nt < 8; nt++)
                mma_fp16(s[nt], qh[kc], &kh4[nt >> 1][(nt & 1) * 2]);
        }

        if (kt == qt) {
            int r0 = wid * 16 + (lane >> 2);
            int r1 = r0 + 8;
#pragma unroll
            for (int nt = 0; nt < 8; nt++) {
                int c0 = nt * 8 + 2 * (lane & 3);
                if (c0 > r0)     s[nt][0] = -1e30f;
                if (c0 + 1 > r0) s[nt][1] = -1e30f;
                if (c0 > r1)     s[nt][2] = -1e30f;
                if (c0 + 1 > r1) s[nt][3] = -1e30f;
            }
        }

        // ---- online softmax ----
        float rm0 = -1e30f, rm1 = -1e30f;
#pragma unroll
        for (int nt = 0; nt < 8; nt++) {
            rm0 = fmaxf(rm0, fmaxf(s[nt][0], s[nt][1]));
            rm1 = fmaxf(rm1, fmaxf(s[nt][2], s[nt][3]));
        }
        rm0 = fmaxf(rm0, __shfl_xor_sync(0xffffffffu, rm0, 1));
        rm0 = fmaxf(rm0, __shfl_xor_sync(0xffffffffu, rm0, 2));
        rm1 = fmaxf(rm1, __shfl_xor_sync(0xffffffffu, rm1, 1));
        rm1 = fmaxf(rm1, __shfl_xor_sync(0xffffffffu, rm1, 2));
        float mn0 = fmaxf(m0, rm0), mn1 = fmaxf(m1, rm1);
        float corr0 = __expf(m0 - mn0), corr1 = __expf(m1 - mn1);
        m0 = mn0; m1 = mn1;

        float sum0 = 0.f, sum1 = 0.f;
#pragma unroll
        for (int nt = 0; nt < 8; nt++) {
            s[nt][0] = __expf(s[nt][0] - mn0);
            s[nt][1] = __expf(s[nt][1] - mn0);
            s[nt][2] = __expf(s[nt][2] - mn1);
            s[nt][3] = __expf(s[nt][3] - mn1);
            sum0 += s[nt][0] + s[nt][1];
            sum1 += s[nt][2] + s[nt][3];
        }
        sum0 += __shfl_xor_sync(0xffffffffu, sum0, 1);
        sum0 += __shfl_xor_sync(0xffffffffu, sum0, 2);
        sum1 += __shfl_xor_sync(0xffffffffu, sum1, 1);
        sum1 += __shfl_xor_sync(0xffffffffu, sum1, 2);
        l0 = l0 * corr0 + sum0;
        l1 = l1 * corr1 + sum1;
#pragma unroll
        for (int nt = 0; nt < 8; nt++) {
            o[nt][0] *= corr0; o[nt][1] *= corr0;
            o[nt][2] *= corr1; o[nt][3] *= corr1;
        }

        // ---- O += P V ----
#pragma unroll
        for (int kc = 0; kc < 4; kc++) {
            const float* sa = s[2 * kc];
            const float* sbv = s[2 * kc + 1];
            uint32_t ph[4];
            ph[0] = pack2h(sa[0], sa[1]);
            ph[1] = pack2h(sa[2], sa[3]);
            ph[2] = pack2h(sbv[0], sbv[1]);
            ph[3] = pack2h(sbv[2], sbv[3]);

            uint32_t vh4[4][4];
#pragma unroll
            for (int p = 0; p < 4; p++)
                ldsm4(vh4[p], bufb + 2304 * 4 + bw + (p * 16 * AS + kc * 8) * 4);
#pragma unroll
            for (int nt = 0; nt < 8; nt++)
                mma_fp16(o[nt], ph, &vh4[nt >> 1][(nt & 1) * 2]);
        }
    }

    // ---- write output plane (fp16) ----
    float inv0 = 1.f / l0, inv1 = 1.f / l1;
    int row = qbase + wid * 16 + (lane >> 2);
#pragma unroll
    for (int nt = 0; nt < 8; nt++) {
        int wc = hw0 + nt * 4 + (lane & 3);
        g_AtP[(size_t)row * KW + wc]       = pack2h(o[nt][0] * inv0, o[nt][1] * inv0);
        g_AtP[(size_t)(row + 8) * KW + wc] = pack2h(o[nt][2] * inv1, o[nt][3] * inv1);
    }
}

// ---------------------------------------------------------------------------
// LayerNorm
// ---------------------------------------------------------------------------
__global__ void ln_kernel(const float* __restrict__ in,
                          const float* __restrict__ gamma,
                          float* __restrict__ out) {
    __shared__ float sbuf[8];
    const int row = blockIdx.x;
    const int t   = threadIdx.x;

    float4 v = *(const float4*)&in[(size_t)row * DIM + (t << 2)];

    float s = v.x + v.y + v.z + v.w;
#pragma unroll
    for (int o = 16; o; o >>= 1) s += __shfl_xor_sync(0xffffffffu, s, o);
    if ((t & 31) == 0) sbuf[t >> 5] = s;
    __syncthreads();
    float tot = sbuf[0] + sbuf[1] + sbuf[2] + sbuf[3] +
                sbuf[4] + sbuf[5] + sbuf[6] + sbuf[7];
    float mean = tot * (1.f / (float)DIM);
    __syncthreads();

    float dx = v.x - mean, dy = v.y - mean, dz = v.z - mean, dw = v.w - mean;
    float s2 = dx * dx + dy * dy + dz * dz + dw * dw;
#pragma unroll
    for (int o = 16; o; o >>= 1) s2 += __shfl_xor_sync(0xffffffffu, s2, o);
    if ((t & 31) == 0) sbuf[t >> 5] = s2;
    __syncthreads();
    float tot2 = sbuf[0] + sbuf[1] + sbuf[2] + sbuf[3] +
                 sbuf[4] + sbuf[5] + sbuf[6] + sbuf[7];
    float rstd = rsqrtf(tot2 * (1.f / (float)DIM) + 1e-5f);

    float4 gm = *(const float4*)&gamma[t << 2];
    float4 r;
    r.x = dx * rstd * gm.x;
    r.y = dy * rstd * gm.y;
    r.z = dz * rstd * gm.z;
    r.w = dw * rstd * gm.w;
    *(float4*)&out[(size_t)row * DIM + (t << 2)] = r;
}

// ---------------------------------------------------------------------------
// launch
// ---------------------------------------------------------------------------
extern "C" void kernel_launch(void* const* d_in, const int* in_sizes, int n_in,
                              void* d_out, int out_size) {
    const float* x     = (const float*)d_in[0];
    const float* Wqkv  = (const float*)d_in[1];
    const float* Wo1   = (const float*)d_in[2];
    const float* Wo2   = (const float*)d_in[3];
    const float* gamma = (const float*)d_in[4];
    float* out = (float*)d_out;

    float *qkv, *h2;
    uint32_t *XP, *AtP, *H1P, *WqkvP, *Wo1P, *Wo2P;
    cudaGetSymbolAddress((void**)&qkv, g_qkv);
    cudaGetSymbolAddress((void**)&h2, g_h2);
    cudaGetSymbolAddress((void**)&XP, g_XP);
    cudaGetSymbolAddress((void**)&AtP, g_AtP);
    cudaGetSymbolAddress((void**)&H1P, g_H1P);
    cudaGetSymbolAddress((void**)&WqkvP, g_WqkvP);
    cudaGetSymbolAddress((void**)&Wo1P, g_Wo1P);
    cudaGetSymbolAddress((void**)&Wo2P, g_Wo2P);

    static bool attr_done = false;
    if (!attr_done) {
        cudaFuncSetAttribute(attn_kernel,
                             cudaFuncAttributeMaxDynamicSharedMemorySize, ATTN_SMEM);
        cudaFuncSetAttribute(gemm_pre<0>,
                             cudaFuncAttributeMaxDynamicSharedMemorySize, GEMM_SMEM);
        cudaFuncSetAttribute(gemm_pre<1>,
                             cudaFuncAttributeMaxDynamicSharedMemorySize, GEMM_SMEM);
        attr_done = true;
    }

    split_x_kernel<<<(N_TOK * KW) / 256, 256>>>(x);
    split_w_kernel<<<dim3(QKV_N / 64, DIM / 64), 256>>>(Wqkv, WqkvP, DIM, QKV_N);
    split_w_kernel<<<dim3(DIM / 64, DIM / 64), 256>>>(Wo1, Wo1P, DIM, DIM);
    split_w_kernel<<<dim3(DIM / 64, DIM / 64), 256>>>(Wo2, Wo2P, DIM, DIM);

    gemm_pre<0><<<dim3(QKV_N / 128, N_TOK / 128), 512, GEMM_SMEM>>>(
        XP, WqkvP, qkv, nullptr, N_TOK, QKV_N, DIM);

    rope_split_kernel<<<(N_TOK * KW) / 256, 256>>>();
    v_prep_kernel<<<dim3(64, HEADS), 256>>>();

    attn_kernel<<<dim3(64, HEADS), 128, ATTN_SMEM>>>();

    gemm_pre<1><<<dim3(DIM / 128, N_TOK / 128), 512, GEMM_SMEM>>>(
        AtP, Wo1P, nullptr, H1P, N_TOK, DIM, DIM);

    gemm_pre<0><<<dim3(DIM / 128, N_TOK / 128), 512, GEMM_SMEM>>>(
        H1P, Wo2P, h2, nullptr, N_TOK, DIM, DIM);

    ln_kernel<<<N_TOK, 256>>>(h2, gamma, out);
}

// round 9
// speedup vs baseline: 12.6467x; 1.0736x over previous
#include <cuda_runtime.h>
#include <cuda_bf16.h>
#include <cuda_fp16.h>
#include <math.h>
#include <stdint.h>

#define N_TOK   4096
#define DIM     1024
#define HEADS   16
#define HD      64
#define QKV_N   3072
#define KW      (DIM / 2)          // 512 packed fp16x2 words per 1024-dim row

// Q pre-scale: (1/sqrt(64)) * log2(e)  -> logits in log2 domain
#define QSCALE  0.180336880111120429f

// ---------------------------------------------------------------------------
// Scratch
// ---------------------------------------------------------------------------
__device__ float    g_qkv[N_TOK * QKV_N];
__device__ float    g_h2[N_TOK * DIM];
__device__ uint32_t g_XP[N_TOK * KW];
__device__ uint32_t g_QP[N_TOK * KW];
__device__ uint32_t g_KP[N_TOK * KW];
__device__ uint32_t g_VP[HEADS * 64 * 2048];
__device__ uint32_t g_AtP[N_TOK * KW];
__device__ uint32_t g_H1P[N_TOK * KW];
__device__ uint32_t g_WqkvP[QKV_N * KW];
__device__ uint32_t g_Wo1P[DIM * KW];
__device__ uint32_t g_Wo2P[DIM * KW];

// ---------------------------------------------------------------------------
// helpers
// ---------------------------------------------------------------------------
__device__ __forceinline__ uint32_t pack2h(float lo, float hi) {
    uint32_t r;
    asm("cvt.rn.f16x2.f32 %0, %1, %2;" : "=r"(r) : "f"(hi), "f"(lo));
    return r;
}
__device__ __forceinline__ float ex2f(float x) {
    float r;
    asm("ex2.approx.f32 %0, %1;" : "=f"(r) : "f"(x));
    return r;
}
__device__ __forceinline__ uint32_t ex2h2(uint32_t x) {
    uint32_t r;
    asm("ex2.approx.f16x2 %0, %1;" : "=r"(r) : "r"(x));
    return r;
}
__device__ __forceinline__ void mma_fp16(float* c, const uint32_t* a, const uint32_t* b) {
    asm volatile("mma.sync.aligned.m16n8k16.row.col.f32.f16.f16.f32 "
        "{%0,%1,%2,%3}, {%4,%5,%6,%7}, {%8,%9}, {%0,%1,%2,%3};"
        : "+f"(c[0]), "+f"(c[1]), "+f"(c[2]), "+f"(c[3])
        : "r"(a[0]), "r"(a[1]), "r"(a[2]), "r"(a[3]), "r"(b[0]), "r"(b[1]));
}
__device__ __forceinline__ void ldsm4(uint32_t* r, uint32_t addr) {
    asm volatile("ldmatrix.sync.aligned.m8n8.x4.shared.b16 {%0,%1,%2,%3}, [%4];"
        : "=r"(r[0]), "=r"(r[1]), "=r"(r[2]), "=r"(r[3]) : "r"(addr));
}
__device__ __forceinline__ uint32_t smem_u32(const void* p) {
    uint32_t a;
    asm("{ .reg .u64 t; cvta.to.shared.u64 t, %1; cvt.u32.u64 %0, t; }"
        : "=r"(a) : "l"(p));
    return a;
}
#define CP_ASYNC16(dst, src) \
    asm volatile("cp.async.cg.shared.global [%0], [%1], 16;" :: "r"(dst), "l"(src))
#define CP_COMMIT() asm volatile("cp.async.commit_group;")
#define CP_WAIT0()  asm volatile("cp.async.wait_group 0;")
#define CP_WAIT1()  asm volatile("cp.async.wait_group 1;")

// ---------------------------------------------------------------------------
// Prep kernels
// ---------------------------------------------------------------------------
__global__ void split_x_kernel(const float* __restrict__ x) {
    int idx = blockIdx.x * 256 + threadIdx.x;
    float2 v = *(const float2*)&x[(size_t)idx * 2];
    g_XP[idx] = pack2h(v.x, v.y);
}

// All three weights in one launch: z selects target. W[K=1024][N] -> P [N][K/2]
__global__ void split_w3_kernel(const float* __restrict__ W0,
                                const float* __restrict__ W1,
                                const float* __restrict__ W2) {
    const int z = blockIdx.z;
    const float* W;
    uint32_t* P;
    int N;
    if (z == 0)      { W = W0; P = g_WqkvP; N = QKV_N; }
    else if (z == 1) { W = W1; P = g_Wo1P;  N = DIM; }
    else             { W = W2; P = g_Wo2P;  N = DIM; }
    const int n0 = blockIdx.x * 64;
    if (n0 >= N) return;
    const int k0 = blockIdx.y * 64;

    __shared__ float S[64][68];
    const int t = threadIdx.x;
#pragma unroll
    for (int i = 0; i < 4; i++) {
        int slot = i * 256 + t;
        int k = slot >> 4, n4 = (slot & 15) << 2;
        *(float4*)&S[k][n4] = *(const float4*)&W[(size_t)(k0 + k) * N + n0 + n4];
    }
    __syncthreads();
#pragma unroll
    for (int i = 0; i < 8; i++) {
        int slot = i * 256 + t;
        int n = slot >> 5, kwl = slot & 31;
        P[(size_t)(n0 + n) * KW + (k0 >> 1) + kwl] = pack2h(S[2 * kwl][n], S[2 * kwl + 1][n]);
    }
}

// RoPE for q,k + V transpose-pack, one block per (kv-tile, head).
__global__ void rope_v_kernel() {
    __shared__ float S[64][68];
    const int t = threadIdx.x;
    const int kt = blockIdx.x, h = blockIdx.y;

    // ---- V transpose-pack ----
#pragma unroll
    for (int i = 0; i < 4; i++) {
        int slot = i * 256 + t;
        int r = slot >> 4, c4 = (slot & 15) << 2;
        *(float4*)&S[r][c4] =
            *(const float4*)&g_qkv[(size_t)(kt * 64 + r) * QKV_N + 2 * DIM + h * HD + c4];
    }
    __syncthreads();
    size_t tb = ((size_t)(h * 64 + kt)) << 11;
#pragma unroll
    for (int i = 0; i < 8; i++) {
        int slot = i * 256 + t;
        int d = slot >> 5, p = slot & 31;
        g_VP[tb + slot] = pack2h(S[2 * p][d], S[2 * p + 1][d]);
    }

    // ---- RoPE for this (tile, head): 64 rows x 32 words ----
#pragma unroll
    for (int i = 0; i < 8; i++) {
        int slot = i * 256 + t;
        int r = slot >> 5, w = slot & 31;
        int row = kt * 64 + r;
        int d0 = w * 2;
        int i0 = d0 & 31;

        float invf0 = powf(10000.f, -(float)i0 * (1.f / 32.f));
        float invf1 = powf(10000.f, -(float)(i0 + 1) * (1.f / 32.f));
        float s0, c0, s1, c1;
        sincosf((float)row * invf0, &s0, &c0);
        sincosf((float)row * invf1, &s1, &c1);

        bool half = (d0 < 32);
        size_t base = (size_t)row * QKV_N + h * HD + d0;
        size_t pb   = half ? base + 32 : base - 32;

        float q0 = g_qkv[base],       q1 = g_qkv[base + 1];
        float qp0 = g_qkv[pb],        qp1 = g_qkv[pb + 1];
        float k0 = g_qkv[base + DIM], k1 = g_qkv[base + DIM + 1];
        float kp0 = g_qkv[pb + DIM],  kp1 = g_qkv[pb + DIM + 1];

        float oq0, oq1, ok0, ok1;
        if (half) {
            oq0 = q0 * c0 - qp0 * s0;  oq1 = q1 * c1 - qp1 * s1;
            ok0 = k0 * c0 - kp0 * s0;  ok1 = k1 * c1 - kp1 * s1;
        } else {
            oq0 = q0 * c0 + qp0 * s0;  oq1 = q1 * c1 + qp1 * s1;
            ok0 = k0 * c0 + kp0 * s0;  ok1 = k1 * c1 + kp1 * s1;
        }
        oq0 *= QSCALE; oq1 *= QSCALE;

        size_t widx = (size_t)row * KW + h * 32 + w;
        g_QP[widx] = pack2h(oq0, oq1);
        g_KP[widx] = pack2h(ok0, ok1);
    }
}

// ---------------------------------------------------------------------------
// GEMM: single fp16 A x single fp16 B, 3-stage cp.async, ldmatrix feeds.
// ---------------------------------------------------------------------------
#define GS 20
#define GEMM_BUF_W (2 * 128 * GS)               // 5120 words
#define GEMM_SMEM  (3 * GEMM_BUF_W * 4)         // 61440 B

template <int MODE>
__global__ void __launch_bounds__(512)
gemm_pre(const uint32_t* __restrict__ AP, const uint32_t* __restrict__ BP,
         float* __restrict__ Cf, uint32_t* __restrict__ CP,
         int M, int N, int K) {
    extern __shared__ uint32_t sw[];
    const int kw = K >> 1;
    const int t = threadIdx.x;
    const int lane = t & 31;
    const int wid = t >> 5;
    const int wm = wid & 3;
    const int wn = wid >> 2;
    const int bm = blockIdx.y * 128;
    const int bn = blockIdx.x * 128;
    const uint32_t sb = smem_u32(sw);

    const int frow = t >> 2;
    const int fw4  = (t & 3) << 2;
    const uint32_t* sAP = &AP[(size_t)(bm + frow) * kw + fw4];
    const uint32_t* sBP = &BP[(size_t)(bn + frow) * kw + fw4];
    const uint32_t dbase = sb + (frow * GS + fw4) * 4;

    auto issue = [&](int c, int b) {
        uint32_t d = dbase + (b * GEMM_BUF_W) * 4;
        int go = c * 16;
        CP_ASYNC16(d,            sAP + go);
        CP_ASYNC16(d + 2560 * 4, sBP + go);
    };

    const uint32_t aw = ((wm * 32 + (lane & 15)) * GS + (lane >> 4) * 4) * 4;
    const int g = lane >> 3;
    const uint32_t bw = ((wn * 32 + (g >> 1) * 8 + (lane & 7)) * GS + (g & 1) * 4) * 4;

    float acc[2][4][4];
#pragma unroll
    for (int i = 0; i < 2; i++)
#pragma unroll
        for (int j = 0; j < 4; j++)
#pragma unroll
            for (int r = 0; r < 4; r++) acc[i][j][r] = 0.f;

    const int nch = K / 32;
    issue(0, 0); CP_COMMIT();
    if (nch > 1) { issue(1, 1); CP_COMMIT(); }

    for (int c = 0; c < nch; c++) {
        if (c + 1 < nch) CP_WAIT1(); else CP_WAIT0();
        __syncthreads();
        if (c + 2 < nch) { issue(c + 2, (c + 2) % 3); CP_COMMIT(); }

        const uint32_t bufb = sb + ((c % 3) * GEMM_BUF_W) * 4;

#pragma unroll
        for (int ks = 0; ks < 2; ks++) {
            uint32_t ah[2][4], bp[2][4];
#pragma unroll
            for (int mt = 0; mt < 2; mt++)
                ldsm4(ah[mt], bufb + aw + (mt * 16 * GS + ks * 8) * 4);
#pragma unroll
            for (int p = 0; p < 2; p++)
                ldsm4(bp[p], bufb + 2560 * 4 + bw + (p * 16 * GS + ks * 8) * 4);
#pragma unroll
            for (int mt = 0; mt < 2; mt++)
#pragma unroll
                for (int nt = 0; nt < 4; nt++)
                    mma_fp16(acc[mt][nt], ah[mt], &bp[nt >> 1][(nt & 1) * 2]);
        }
    }

#pragma unroll
    for (int mt = 0; mt < 2; mt++)
#pragma unroll
        for (int nt = 0; nt < 4; nt++) {
            int row = bm + wm * 32 + mt * 16 + (lane >> 2);
            int col = bn + wn * 32 + nt * 8 + 2 * (lane & 3);
            float v0 = acc[mt][nt][0], v1 = acc[mt][nt][1];
            float v2 = acc[mt][nt][2], v3 = acc[mt][nt][3];
            if (MODE == 1) {
                v0 = fmaxf(v0, 0.f); v1 = fmaxf(v1, 0.f);
                v2 = fmaxf(v2, 0.f); v3 = fmaxf(v3, 0.f);
                int wc = col >> 1;
                CP[(size_t)row * (N >> 1) + wc]       = pack2h(v0, v1);
                CP[(size_t)(row + 8) * (N >> 1) + wc] = pack2h(v2, v3);
            } else {
                *(float2*)&Cf[(size_t)row * N + col]       = make_float2(v0, v1);
                *(float2*)&Cf[(size_t)(row + 8) * N + col] = make_float2(v2, v3);
            }
        }
}

// ---------------------------------------------------------------------------
// Flash attention (log2-domain softmax, packed fp16 ex2, mma row-sums).
// Per buffer (words): K[64*36] @0, V @2304 -> 4608 (18 KB), 3 buffers.
// ---------------------------------------------------------------------------
#define AS 36
#define BUFW 4608
#define ATTN_SMEM (3 * BUFW * 4)     // 55296 B

__global__ void __launch_bounds__(128)
attn_kernel() {
    extern __shared__ uint32_t sw[];
    const uint32_t sb = smem_u32(sw);

    const int t = threadIdx.x;
    const int lane = t & 31;
    const int wid = t >> 5;
    const int h = blockIdx.y;
    const int qt = (int)gridDim.x - 1 - (int)blockIdx.x;
    const int qbase = qt * 64;
    const int hw0 = h * 32;

    // ---- stage Q, extract frags ----
#pragma unroll
    for (int i = 0; i < 8; i++) {
        int idx = i * 128 + t;
        int row = idx >> 4;
        int w2  = (idx & 15) << 1;
        *(uint2*)&sw[row * AS + w2] =
            *(const uint2*)&g_QP[(size_t)(qbase + row) * KW + hw0 + w2];
    }
    __syncthreads();

    uint32_t qh[4][4];
    {
        uint32_t qa = sb + ((wid * 16 + (lane & 15)) * AS + (lane >> 4) * 4) * 4;
#pragma unroll
        for (int kc = 0; kc < 4; kc++)
            ldsm4(qh[kc], qa + kc * 32);
    }
    __syncthreads();

    const int g = lane >> 3;
    const uint32_t bw = (((g >> 1) * 8 + (lane & 7)) * AS + (g & 1) * 4) * 4;

    auto issueKV = [&](int kt, int b) {
        uint32_t dstb = sb + (b * BUFW) * 4;
        size_t krow = (size_t)kt * 64;
        size_t tb = ((size_t)(h * 64 + kt)) << 11;
#pragma unroll
        for (int j = 0; j < 4; j++) {
            int idx = j * 128 + t;
            int row = idx >> 3;
            int seg = (idx & 7) << 2;
            uint32_t d0 = dstb + (row * AS + seg) * 4;
            CP_ASYNC16(d0,            &g_KP[(krow + row) * KW + hw0 + seg]);
            CP_ASYNC16(d0 + 2304 * 4, &g_VP[tb + row * 32 + seg]);
        }
    };

    float o[8][4];
#pragma unroll
    for (int nt = 0; nt < 8; nt++)
#pragma unroll
        for (int r = 0; r < 4; r++) o[nt][r] = 0.f;
    float m0 = -1e30f, m1 = -1e30f, l0 = 0.f, l1 = 0.f;

    const uint32_t ones2[2] = {0x3C003C00u, 0x3C003C00u};

    issueKV(0, 0); CP_COMMIT();
    if (qt >= 1) { issueKV(1, 1); CP_COMMIT(); }

    for (int kt = 0; kt <= qt; kt++) {
        if (kt < qt) CP_WAIT1(); else CP_WAIT0();
        __syncthreads();
        if (kt + 2 <= qt) { issueKV(kt + 2, (kt + 2) % 3); CP_COMMIT(); }

        const uint32_t bufb = sb + ((kt % 3) * BUFW) * 4;

        // ---- S = Q K^T (log2-domain logits) ----
        float s[8][4];
#pragma unroll
        for (int nt = 0; nt < 8; nt++)
#pragma unroll
            for (int r = 0; r < 4; r++) s[nt][r] = 0.f;

#pragma unroll
        for (int kc = 0; kc < 4; kc++) {
            uint32_t kh4[4][4];
#pragma unroll
            for (int p = 0; p < 4; p++)
                ldsm4(kh4[p], bufb + bw + (p * 16 * AS + kc * 8) * 4);
#pragma unroll
            for (int nt = 0; nt < 8; nt++)
                mma_fp16(s[nt], qh[kc], &kh4[nt >> 1][(nt & 1) * 2]);
        }

        if (kt == qt) {
            int r0 = wid * 16 + (lane >> 2);
            int r1 = r0 + 8;
#pragma unroll
            for (int nt = 0; nt < 8; nt++) {
                int c0 = nt * 8 + 2 * (lane & 3);
                if (c0 > r0)     s[nt][0] = -1e30f;
                if (c0 + 1 > r0) s[nt][1] = -1e30f;
                if (c0 > r1)     s[nt][2] = -1e30f;
                if (c0 + 1 > r1) s[nt][3] = -1e30f;
            }
        }

        // ---- online softmax (log2 domain) ----
        float rm0 = -1e30f, rm1 = -1e30f;
#pragma unroll
        for (int nt = 0; nt < 8; nt++) {
            rm0 = fmaxf(rm0, fmaxf(s[nt][0], s[nt][1]));
            rm1 = fmaxf(rm1, fmaxf(s[nt][2], s[nt][3]));
        }
        rm0 = fmaxf(rm0, __shfl_xor_sync(0xffffffffu, rm0, 1));
        rm0 = fmaxf(rm0, __shfl_xor_sync(0xffffffffu, rm0, 2));
        rm1 = fmaxf(rm1, __shfl_xor_sync(0xffffffffu, rm1, 1));
        rm1 = fmaxf(rm1, __shfl_xor_sync(0xffffffffu, rm1, 2));
        float mn0 = fmaxf(m0, rm0), mn1 = fmaxf(m1, rm1);
        float corr0 = ex2f(m0 - mn0), corr1 = ex2f(m1 - mn1);
        m0 = mn0; m1 = mn1;

        // P = 2^(s - mn), computed packed in fp16
        uint32_t ph[4][4];
#pragma unroll
        for (int nt = 0; nt < 8; nt++) {
            uint32_t p01 = ex2h2(pack2h(s[nt][0] - mn0, s[nt][1] - mn0));
            uint32_t p23 = ex2h2(pack2h(s[nt][2] - mn1, s[nt][3] - mn1));
            ph[nt >> 1][(nt & 1) * 2 + 0] = p01;
            ph[nt >> 1][(nt & 1) * 2 + 1] = p23;
        }

        // row sums via mma with all-ones B
        float lacc[4] = {0.f, 0.f, 0.f, 0.f};
#pragma unroll
        for (int kc = 0; kc < 4; kc++)
            mma_fp16(lacc, ph[kc], ones2);
        l0 = l0 * corr0 + lacc[0];
        l1 = l1 * corr1 + lacc[2];

#pragma unroll
        for (int nt = 0; nt < 8; nt++) {
            o[nt][0] *= corr0; o[nt][1] *= corr0;
            o[nt][2] *= corr1; o[nt][3] *= corr1;
        }

        // ---- O += P V ----
#pragma unroll
        for (int kc = 0; kc < 4; kc++) {
            uint32_t vh4[4][4];
#pragma unroll
            for (int p = 0; p < 4; p++)
                ldsm4(vh4[p], bufb + 2304 * 4 + bw + (p * 16 * AS + kc * 8) * 4);
#pragma unroll
            for (int nt = 0; nt < 8; nt++)
                mma_fp16(o[nt], ph[kc], &vh4[nt >> 1][(nt & 1) * 2]);
        }
    }

    // ---- write output plane (fp16) ----
    float inv0 = 1.f / l0, inv1 = 1.f / l1;
    int row = qbase + wid * 16 + (lane >> 2);
#pragma unroll
    for (int nt = 0; nt < 8; nt++) {
        int wc = hw0 + nt * 4 + (lane & 3);
        g_AtP[(size_t)row * KW + wc]       = pack2h(o[nt][0] * inv0, o[nt][1] * inv0);
        g_AtP[(size_t)(row + 8) * KW + wc] = pack2h(o[nt][2] * inv1, o[nt][3] * inv1);
    }
}

// ---------------------------------------------------------------------------
// LayerNorm
// ---------------------------------------------------------------------------
__global__ void ln_kernel(const float* __restrict__ in,
                          const float* __restrict__ gamma,
                          float* __restrict__ out) {
    __shared__ float sbuf[8];
    const int row = blockIdx.x;
    const int t   = threadIdx.x;

    float4 v = *(const float4*)&in[(size_t)row * DIM + (t << 2)];

    float s = v.x + v.y + v.z + v.w;
#pragma unroll
    for (int o = 16; o; o >>= 1) s += __shfl_xor_sync(0xffffffffu, s, o);
    if ((t & 31) == 0) sbuf[t >> 5] = s;
    __syncthreads();
    float tot = sbuf[0] + sbuf[1] + sbuf[2] + sbuf[3] +
                sbuf[4] + sbuf[5] + sbuf[6] + sbuf[7];
    float mean = tot * (1.f / (float)DIM);
    __syncthreads();

    float dx = v.x - mean, dy = v.y - mean, dz = v.z - mean, dw = v.w - mean;
    float s2 = dx * dx + dy * dy + dz * dz + dw * dw;
#pragma unroll
    for (int o = 16; o; o >>= 1) s2 += __shfl_xor_sync(0xffffffffu, s2, o);
    if ((t & 31) == 0) sbuf[t >> 5] = s2;
    __syncthreads();
    float tot2 = sbuf[0] + sbuf[1] + sbuf[2] + sbuf[3] +
                 sbuf[4] + sbuf[5] + sbuf[6] + sbuf[7];
    float rstd = rsqrtf(tot2 * (1.f / (float)DIM) + 1e-5f);

    float4 gm = *(const float4*)&gamma[t << 2];
    float4 r;
    r.x = dx * rstd * gm.x;
    r.y = dy * rstd * gm.y;
    r.z = dz * rstd * gm.z;
    r.w = dw * rstd * gm.w;
    *(float4*)&out[(size_t)row * DIM + (t << 2)] = r;
}

// ---------------------------------------------------------------------------
// launch
// ---------------------------------------------------------------------------
extern "C" void kernel_launch(void* const* d_in, const int* in_sizes, int n_in,
                              void* d_out, int out_size) {
    const float* x     = (const float*)d_in[0];
    const float* Wqkv  = (const float*)d_in[1];
    const float* Wo1   = (const float*)d_in[2];
    const float* Wo2   = (const float*)d_in[3];
    const float* gamma = (const float*)d_in[4];
    float* out = (float*)d_out;

    float *qkv, *h2;
    uint32_t *XP, *AtP, *H1P, *WqkvP, *Wo1P, *Wo2P;
    cudaGetSymbolAddress((void**)&qkv, g_qkv);
    cudaGetSymbolAddress((void**)&h2, g_h2);
    cudaGetSymbolAddress((void**)&XP, g_XP);
    cudaGetSymbolAddress((void**)&AtP, g_AtP);
    cudaGetSymbolAddress((void**)&H1P, g_H1P);
    cudaGetSymbolAddress((void**)&WqkvP, g_WqkvP);
    cudaGetSymbolAddress((void**)&Wo1P, g_Wo1P);
    cudaGetSymbolAddress((void**)&Wo2P, g_Wo2P);

    static bool attr_done = false;
    if (!attr_done) {
        cudaFuncSetAttribute(attn_kernel,
                             cudaFuncAttributeMaxDynamicSharedMemorySize, ATTN_SMEM);
        cudaFuncSetAttribute(gemm_pre<0>,
                             cudaFuncAttributeMaxDynamicSharedMemorySize, GEMM_SMEM);
        cudaFuncSetAttribute(gemm_pre<1>,
                             cudaFuncAttributeMaxDynamicSharedMemorySize, GEMM_SMEM);
        attr_done = true;
    }

    split_x_kernel<<<(N_TOK * KW) / 256, 256>>>(x);
    split_w3_kernel<<<dim3(QKV_N / 64, DIM / 64, 3), 256>>>(Wqkv, Wo1, Wo2);

    gemm_pre<0><<<dim3(QKV_N / 128, N_TOK / 128), 512, GEMM_SMEM>>>(
        XP, WqkvP, qkv, nullptr, N_TOK, QKV_N, DIM);

    rope_v_kernel<<<dim3(64, HEADS), 256>>>();

    attn_kernel<<<dim3(64, HEADS), 128, ATTN_SMEM>>>();

    gemm_pre<1><<<dim3(DIM / 128, N_TOK / 128), 512, GEMM_SMEM>>>(
        AtP, Wo1P, nullptr, H1P, N_TOK, DIM, DIM);

    gemm_pre<0><<<dim3(DIM / 128, N_TOK / 128), 512, GEMM_SMEM>>>(
        H1P, Wo2P, h2, nullptr, N_TOK, DIM, DIM);

    ln_kernel<<<N_TOK, 256>>>(h2, gamma, out);
}